// round 6
// baseline (speedup 1.0000x reference)
#include <cuda_runtime.h>
#include <cuda_bf16.h>
#include <float.h>
#include <math.h>
#include <stdint.h>

#define NN 50000
#define DD 128
#define HH 8
#define HDIM 16
#define EE 800000
#define EDIM 4
#define GROUPS 8
#define EPS_GN 1e-5f

// ---------------- scratch (static device globals; no allocation) ----------------
__device__ __align__(16) float g_q[NN * DD];
__device__ __align__(16) float g_k[NN * DD];
__device__ __align__(16) float g_v[NN * DD];
__device__ __align__(16) float g_agg[NN * DD];
__device__ int g_deg[NN];
__device__ int g_cur[NN];
__device__ int g_off[NN + 1];
__device__ int g_csr_src[EE];
__device__ __align__(16) float g_csr_bias[(size_t)EE * HH];

// ---------------- tf32 helpers ----------------
__device__ __forceinline__ uint32_t f32_to_tf32(float f) {
    uint32_t r;
    asm("cvt.rna.tf32.f32 %0, %1;" : "=r"(r) : "f"(f));
    return r;
}

__device__ __forceinline__ void mma_tf32(float* c, const uint32_t* a, const uint32_t* b) {
    asm volatile(
        "mma.sync.aligned.m16n8k8.row.col.f32.tf32.tf32.f32 "
        "{%0,%1,%2,%3}, {%4,%5,%6,%7}, {%8,%9}, {%0,%1,%2,%3};"
        : "+f"(c[0]), "+f"(c[1]), "+f"(c[2]), "+f"(c[3])
        : "r"(a[0]), "r"(a[1]), "r"(a[2]), "r"(a[3]), "r"(b[0]), "r"(b[1]));
}

// ---------------- CSR build ----------------
__global__ void zero_kernel() {
    int i = blockIdx.x * blockDim.x + threadIdx.x;
    if (i < NN) { g_deg[i] = 0; g_cur[i] = 0; }
}

__global__ void hist_kernel(const int* __restrict__ ei) {
    int e = blockIdx.x * blockDim.x + threadIdx.x;
    if (e >= EE) return;
    atomicAdd(&g_deg[ei[EE + e]], 1);
}

// single-block exclusive scan of g_deg -> g_off
__global__ void scan_kernel() {
    __shared__ int sdata[1024];
    __shared__ int s_running;
    const int tid = threadIdx.x;
    if (tid == 0) s_running = 0;
    __syncthreads();

    for (int base = 0; base < NN; base += 1024) {
        int v = (base + tid < NN) ? g_deg[base + tid] : 0;
        sdata[tid] = v;
        __syncthreads();
#pragma unroll
        for (int s = 1; s < 1024; s <<= 1) {
            int t = (tid >= s) ? sdata[tid - s] : 0;
            __syncthreads();
            sdata[tid] += t;
            __syncthreads();
        }
        int incl = sdata[tid];
        int run = s_running;
        if (base + tid < NN) g_off[base + tid] = run + incl - v;
        __syncthreads();
        if (tid == 0) s_running = run + sdata[1023];
        __syncthreads();
    }
    if (tid == 0) g_off[NN] = s_running;
}

// scatter edges into CSR slots; precompute per-edge head bias in CSR order
__global__ void scatter_kernel(const int* __restrict__ ei,
                               const float* __restrict__ edge_attr,
                               const float* __restrict__ We,
                               const float* __restrict__ be) {
    int e = blockIdx.x * blockDim.x + threadIdx.x;
    if (e >= EE) return;
    int src = ei[e];
    int dst = ei[EE + e];
    int slot = g_off[dst] + atomicAdd(&g_cur[dst], 1);
    g_csr_src[slot] = src;

    float4 ea = ((const float4*)edge_attr)[e];
    float* bias = &g_csr_bias[(size_t)slot * HH];
#pragma unroll
    for (int h = 0; h < HH; h += 4) {
        float4 o;
        o.x = ea.x * We[0 * HH + h + 0] + ea.y * We[1 * HH + h + 0]
            + ea.z * We[2 * HH + h + 0] + ea.w * We[3 * HH + h + 0] + be[h + 0];
        o.y = ea.x * We[0 * HH + h + 1] + ea.y * We[1 * HH + h + 1]
            + ea.z * We[2 * HH + h + 1] + ea.w * We[3 * HH + h + 1] + be[h + 1];
        o.z = ea.x * We[0 * HH + h + 2] + ea.y * We[1 * HH + h + 2]
            + ea.z * We[2 * HH + h + 2] + ea.w * We[3 * HH + h + 2] + be[h + 2];
        o.w = ea.x * We[0 * HH + h + 3] + ea.y * We[1 * HH + h + 3]
            + ea.z * We[2 * HH + h + 3] + ea.w * We[3 * HH + h + 3] + be[h + 3];
        *(float4*)(bias + h) = o;
    }
}

// ---------------- tf32 tensor-core Q/K/V GEMM ----------------
#define XS_STRIDE 44
#define WS_STRIDE 136

__global__ void __launch_bounds__(256) qkv_tc_kernel(
        const float* __restrict__ x,
        const float* __restrict__ Wq, const float* __restrict__ bq,
        const float* __restrict__ Wk, const float* __restrict__ bk,
        const float* __restrict__ Wv, const float* __restrict__ bv) {
    __shared__ float xs[128 * XS_STRIDE];
    __shared__ float ws[32 * WS_STRIDE];

    const int tid  = threadIdx.x;
    const int wid  = tid >> 5;
    const int lane = tid & 31;
    const int g    = lane >> 2;
    const int tg   = lane & 3;
    const int row0 = blockIdx.x * 128;
    const int wm0  = (wid >> 1) * 32;
    const int wn0  = (wid & 1) * 64;

    const float* Ws[3] = {Wq, Wk, Wv};
    const float* bs[3] = {bq, bk, bv};
    float* outs[3];
    outs[0] = g_q; outs[1] = g_k; outs[2] = g_v;

#pragma unroll 1
    for (int which = 0; which < 3; which++) {
        const float* W = Ws[which];
        const float* bb = bs[which];
        float* out = outs[which];

        float acc[2][8][4];
#pragma unroll
        for (int nt = 0; nt < 8; nt++) {
            int n = wn0 + nt * 8 + tg * 2;
            float b0 = bb[n], b1 = bb[n + 1];
#pragma unroll
            for (int mt = 0; mt < 2; mt++) {
                acc[mt][nt][0] = b0; acc[mt][nt][1] = b1;
                acc[mt][nt][2] = b0; acc[mt][nt][3] = b1;
            }
        }

#pragma unroll 1
        for (int kk = 0; kk < 128; kk += 32) {
            __syncthreads();
            for (int i = tid; i < 128 * 8; i += 256) {
                int r = i >> 3, c4 = i & 7;
                float4 v = make_float4(0.f, 0.f, 0.f, 0.f);
                if (row0 + r < NN)
                    v = ((const float4*)x)[(size_t)(row0 + r) * 32 + (kk >> 2) + c4];
                uint32_t* d = (uint32_t*)(xs + r * XS_STRIDE + c4 * 4);
                d[0] = f32_to_tf32(v.x); d[1] = f32_to_tf32(v.y);
                d[2] = f32_to_tf32(v.z); d[3] = f32_to_tf32(v.w);
            }
            for (int i = tid; i < 32 * 32; i += 256) {
                int r = i >> 5, c4 = i & 31;
                float4 v = ((const float4*)W)[(size_t)(kk + r) * 32 + c4];
                uint32_t* d = (uint32_t*)(ws + r * WS_STRIDE + c4 * 4);
                d[0] = f32_to_tf32(v.x); d[1] = f32_to_tf32(v.y);
                d[2] = f32_to_tf32(v.z); d[3] = f32_to_tf32(v.w);
            }
            __syncthreads();

#pragma unroll
            for (int kk2 = 0; kk2 < 32; kk2 += 8) {
                uint32_t afr[2][4];
#pragma unroll
                for (int mt = 0; mt < 2; mt++) {
                    const uint32_t* xr  = (const uint32_t*)(xs + (wm0 + mt * 16 + g) * XS_STRIDE + kk2);
                    const uint32_t* xr8 = (const uint32_t*)(xs + (wm0 + mt * 16 + g + 8) * XS_STRIDE + kk2);
                    afr[mt][0] = xr[tg];
                    afr[mt][1] = xr8[tg];
                    afr[mt][2] = xr[tg + 4];
                    afr[mt][3] = xr8[tg + 4];
                }
#pragma unroll
                for (int nt = 0; nt < 8; nt++) {
                    uint32_t bfr[2];
                    bfr[0] = ((const uint32_t*)(ws + (kk2 + tg) * WS_STRIDE))[wn0 + nt * 8 + g];
                    bfr[1] = ((const uint32_t*)(ws + (kk2 + tg + 4) * WS_STRIDE))[wn0 + nt * 8 + g];
                    mma_tf32(acc[0][nt], afr[0], bfr);
                    mma_tf32(acc[1][nt], afr[1], bfr);
                }
            }
        }

        __syncthreads();
#pragma unroll
        for (int mt = 0; mt < 2; mt++) {
            int rA = row0 + wm0 + mt * 16 + g;
            int rB = rA + 8;
#pragma unroll
            for (int nt = 0; nt < 8; nt++) {
                int n = wn0 + nt * 8 + tg * 2;
                if (rA < NN)
                    *(float2*)(out + (size_t)rA * 128 + n) = make_float2(acc[mt][nt][0], acc[mt][nt][1]);
                if (rB < NN)
                    *(float2*)(out + (size_t)rB * 128 + n) = make_float2(acc[mt][nt][2], acc[mt][nt][3]);
            }
        }
    }
}

// ---------------- fused gather: logits -> exp -> weighted sum -> normalize ----
// one warp per dst node; lane = 4 dims, head = lane/4. No atomics.
__global__ void __launch_bounds__(256) gather_kernel() {
    int node = blockIdx.x * 8 + (threadIdx.x >> 5);
    if (node >= NN) return;
    int lane = threadIdx.x & 31;
    int h = lane >> 2;

    float4 q4 = ((const float4*)g_q)[(size_t)node * 32 + lane];
    int o  = g_off[node];
    int dg = g_deg[node];

    float4 acc = make_float4(0.f, 0.f, 0.f, 0.f);
    float sh = 0.f;

    for (int j = 0; j < dg; j++) {
        int src = g_csr_src[o + j];
        float bias = g_csr_bias[(size_t)(o + j) * HH + h];
        float4 k4 = ((const float4*)g_k)[(size_t)src * 32 + lane];
        float p = q4.x * k4.x + q4.y * k4.y + q4.z * k4.z + q4.w * k4.w;
        p += __shfl_xor_sync(0xffffffffu, p, 1);
        p += __shfl_xor_sync(0xffffffffu, p, 2);
        float ex = __expf(p * 0.25f + bias);
        sh += ex;
        float4 v4 = ((const float4*)g_v)[(size_t)src * 32 + lane];
        acc.x = fmaf(ex, v4.x, acc.x);
        acc.y = fmaf(ex, v4.y, acc.y);
        acc.z = fmaf(ex, v4.z, acc.z);
        acc.w = fmaf(ex, v4.w, acc.w);
    }

    float inv = 1.0f / fmaxf(sh, 1e-6f);
    acc.x *= inv; acc.y *= inv; acc.z *= inv; acc.w *= inv;
    ((float4*)g_agg)[(size_t)node * 32 + lane] = acc;
}

// ---------------- Wo GEMM + GroupNorm epilogue (fp32 SIMT) ---------
__global__ void out_gn_kernel(const float* __restrict__ Wo, const float* __restrict__ bo,
                              const float* __restrict__ gamma, const float* __restrict__ beta,
                              float* __restrict__ out) {
    __shared__ float xs[32 * 128];
    __shared__ float ws[64 * 128];

    const int row0 = blockIdx.x * 32;
    const int tid  = threadIdx.x;

    for (int i = tid; i < 32 * 32; i += 256) {
        int r  = i >> 5;
        int c4 = i & 31;
        float4 val = make_float4(0.f, 0.f, 0.f, 0.f);
        if (row0 + r < NN) val = ((const float4*)g_agg)[(size_t)(row0 + r) * 32 + c4];
        ((float4*)xs)[i] = val;
    }

    const int trow = tid >> 5;
    const int tcol = tid & 31;
    const int r = trow * 4;
    const int c = tcol * 4;

    float acc[4][4];
#pragma unroll
    for (int i = 0; i < 4; i++) {
#pragma unroll
        for (int j = 0; j < 4; j++) acc[i][j] = bo[c + j];
    }

#pragma unroll 1
    for (int kk = 0; kk < 128; kk += 64) {
        __syncthreads();
        for (int i = tid; i < 64 * 32; i += 256)
            ((float4*)ws)[i] = ((const float4*)Wo)[kk * 32 + i];
        __syncthreads();

#pragma unroll 8
        for (int k = 0; k < 64; k++) {
            float4 wv4 = ((float4*)ws)[k * 32 + tcol];
#pragma unroll
            for (int i = 0; i < 4; i++) {
                float a = xs[(r + i) * 128 + kk + k];
                acc[i][0] = fmaf(a, wv4.x, acc[i][0]);
                acc[i][1] = fmaf(a, wv4.y, acc[i][1]);
                acc[i][2] = fmaf(a, wv4.z, acc[i][2]);
                acc[i][3] = fmaf(a, wv4.w, acc[i][3]);
            }
        }
    }

    __syncthreads();
#pragma unroll
    for (int i = 0; i < 4; i++) {
#pragma unroll
        for (int j = 0; j < 4; j++) xs[(r + i) * 128 + c + j] = acc[i][j];
    }
    __syncthreads();

    int srow = tid >> 3;
    int grp  = tid & 7;
    float s = 0.f, s2 = 0.f;
#pragma unroll
    for (int j = 0; j < 16; j++) {
        float v = xs[srow * 128 + grp * 16 + j];
        s += v;
        s2 += v * v;
    }
    float mu  = s * (1.0f / 16.0f);
    float var = s2 * (1.0f / 16.0f) - mu * mu;
    float inv = rsqrtf(var + EPS_GN);

    if (row0 + srow < NN) {
        float* orow = out + (size_t)(row0 + srow) * 128;
#pragma unroll
        for (int j4 = 0; j4 < 4; j4++) {
            int ch0 = grp * 16 + j4 * 4;
            float4 g4 = ((const float4*)gamma)[ch0 >> 2];
            float4 b4 = ((const float4*)beta)[ch0 >> 2];
            float4 o;
            o.x = (xs[srow * 128 + ch0 + 0] - mu) * inv * g4.x + b4.x;
            o.y = (xs[srow * 128 + ch0 + 1] - mu) * inv * g4.y + b4.y;
            o.z = (xs[srow * 128 + ch0 + 2] - mu) * inv * g4.z + b4.z;
            o.w = (xs[srow * 128 + ch0 + 3] - mu) * inv * g4.w + b4.w;
            ((float4*)orow)[ch0 >> 2] = o;
        }
    }
}

// ---------------- launch ----------------
extern "C" void kernel_launch(void* const* d_in, const int* in_sizes, int n_in,
                              void* d_out, int out_size) {
    const float* x         = (const float*)d_in[0];
    const int*   ei        = (const int*)d_in[1];   // int32 (JAX downcasts int64 w/o x64 mode)
    const float* edge_attr = (const float*)d_in[2];
    const float* Wq        = (const float*)d_in[3];
    const float* bq        = (const float*)d_in[4];
    const float* Wk        = (const float*)d_in[5];
    const float* bk        = (const float*)d_in[6];
    const float* Wv        = (const float*)d_in[7];
    const float* bv        = (const float*)d_in[8];
    const float* We        = (const float*)d_in[9];
    const float* be        = (const float*)d_in[10];
    const float* Wo        = (const float*)d_in[11];
    const float* bo        = (const float*)d_in[12];
    const float* gamma     = (const float*)d_in[13];
    const float* beta      = (const float*)d_in[14];
    float* out = (float*)d_out;

    // CSR build
    zero_kernel<<<(NN + 255) / 256, 256>>>();
    hist_kernel<<<(EE + 255) / 256, 256>>>(ei);
    scan_kernel<<<1, 1024>>>();
    scatter_kernel<<<(EE + 255) / 256, 256>>>(ei, edge_attr, We, be);

    // projections
    qkv_tc_kernel<<<(NN + 127) / 128, 256>>>(x, Wq, bq, Wk, bk, Wv, bv);

    // fused attention gather (no atomics)
    gather_kernel<<<(NN + 7) / 8, 256>>>();

    // output projection + GroupNorm
    out_gn_kernel<<<(NN + 31) / 32, 256>>>(Wo, bo, gamma, beta, out);
}

// round 7
// speedup vs baseline: 1.0055x; 1.0055x over previous
#include <cuda_runtime.h>
#include <cuda_bf16.h>
#include <float.h>
#include <math.h>
#include <stdint.h>

#define NN 50000
#define DD 128
#define HH 8
#define HDIM 16
#define EE 800000
#define EDIM 4
#define GROUPS 8
#define EPS_GN 1e-5f

// ---------------- scratch (static device globals; no allocation) ----------------
__device__ __align__(16) float g_q[NN * DD];
__device__ __align__(16) float g_k[NN * DD];
__device__ __align__(16) float g_v[NN * DD];
__device__ __align__(16) float g_agg[NN * DD];
__device__ int g_deg[NN];
__device__ int g_cur[NN];
__device__ int g_off[NN + 1];
__device__ int g_csr_src[EE];
__device__ __align__(16) float g_csr_bias[(size_t)EE * HH];

// ---------------- tf32 helpers ----------------
__device__ __forceinline__ uint32_t f32_to_tf32(float f) {
    uint32_t r;
    asm("cvt.rna.tf32.f32 %0, %1;" : "=r"(r) : "f"(f));
    return r;
}

__device__ __forceinline__ void mma_tf32(float* c, const uint32_t* a, const uint32_t* b) {
    asm volatile(
        "mma.sync.aligned.m16n8k8.row.col.f32.tf32.tf32.f32 "
        "{%0,%1,%2,%3}, {%4,%5,%6,%7}, {%8,%9}, {%0,%1,%2,%3};"
        : "+f"(c[0]), "+f"(c[1]), "+f"(c[2]), "+f"(c[3])
        : "r"(a[0]), "r"(a[1]), "r"(a[2]), "r"(a[3]), "r"(b[0]), "r"(b[1]));
}

// ---------------- CSR build ----------------
__global__ void zero_kernel() {
    int i = blockIdx.x * blockDim.x + threadIdx.x;
    if (i < NN) { g_deg[i] = 0; g_cur[i] = 0; }
}

__global__ void hist_kernel(const int* __restrict__ ei) {
    int e = blockIdx.x * blockDim.x + threadIdx.x;
    if (e >= EE) return;
    atomicAdd(&g_deg[ei[EE + e]], 1);
}

// single-block exclusive scan of g_deg -> g_off
__global__ void scan_kernel() {
    __shared__ int sdata[1024];
    __shared__ int s_running;
    const int tid = threadIdx.x;
    if (tid == 0) s_running = 0;
    __syncthreads();

    for (int base = 0; base < NN; base += 1024) {
        int v = (base + tid < NN) ? g_deg[base + tid] : 0;
        sdata[tid] = v;
        __syncthreads();
#pragma unroll
        for (int s = 1; s < 1024; s <<= 1) {
            int t = (tid >= s) ? sdata[tid - s] : 0;
            __syncthreads();
            sdata[tid] += t;
            __syncthreads();
        }
        int incl = sdata[tid];
        int run = s_running;
        if (base + tid < NN) g_off[base + tid] = run + incl - v;
        __syncthreads();
        if (tid == 0) s_running = run + sdata[1023];
        __syncthreads();
    }
    if (tid == 0) g_off[NN] = s_running;
}

// scatter edges into CSR slots; precompute per-edge head bias in CSR order
__global__ void scatter_kernel(const int* __restrict__ ei,
                               const float* __restrict__ edge_attr,
                               const float* __restrict__ We,
                               const float* __restrict__ be) {
    int e = blockIdx.x * blockDim.x + threadIdx.x;
    if (e >= EE) return;
    int src = ei[e];
    int dst = ei[EE + e];
    int slot = g_off[dst] + atomicAdd(&g_cur[dst], 1);
    g_csr_src[slot] = src;

    float4 ea = ((const float4*)edge_attr)[e];
    float* bias = &g_csr_bias[(size_t)slot * HH];
#pragma unroll
    for (int h = 0; h < HH; h += 4) {
        float4 o;
        o.x = ea.x * We[0 * HH + h + 0] + ea.y * We[1 * HH + h + 0]
            + ea.z * We[2 * HH + h + 0] + ea.w * We[3 * HH + h + 0] + be[h + 0];
        o.y = ea.x * We[0 * HH + h + 1] + ea.y * We[1 * HH + h + 1]
            + ea.z * We[2 * HH + h + 1] + ea.w * We[3 * HH + h + 1] + be[h + 1];
        o.z = ea.x * We[0 * HH + h + 2] + ea.y * We[1 * HH + h + 2]
            + ea.z * We[2 * HH + h + 2] + ea.w * We[3 * HH + h + 2] + be[h + 2];
        o.w = ea.x * We[0 * HH + h + 3] + ea.y * We[1 * HH + h + 3]
            + ea.z * We[2 * HH + h + 3] + ea.w * We[3 * HH + h + 3] + be[h + 3];
        *(float4*)(bias + h) = o;
    }
}

// ---------------- tf32 tensor-core Q/K/V GEMM ----------------
#define XS_STRIDE 44
#define WS_STRIDE 136

__global__ void __launch_bounds__(256) qkv_tc_kernel(
        const float* __restrict__ x,
        const float* __restrict__ Wq, const float* __restrict__ bq,
        const float* __restrict__ Wk, const float* __restrict__ bk,
        const float* __restrict__ Wv, const float* __restrict__ bv) {
    __shared__ float xs[128 * XS_STRIDE];
    __shared__ float ws[32 * WS_STRIDE];

    const int tid  = threadIdx.x;
    const int wid  = tid >> 5;
    const int lane = tid & 31;
    const int g    = lane >> 2;
    const int tg   = lane & 3;
    const int row0 = blockIdx.x * 128;
    const int wm0  = (wid >> 1) * 32;
    const int wn0  = (wid & 1) * 64;

    const float* Ws[3] = {Wq, Wk, Wv};
    const float* bs[3] = {bq, bk, bv};
    float* outs[3];
    outs[0] = g_q; outs[1] = g_k; outs[2] = g_v;

#pragma unroll 1
    for (int which = 0; which < 3; which++) {
        const float* W = Ws[which];
        const float* bb = bs[which];
        float* out = outs[which];

        float acc[2][8][4];
#pragma unroll
        for (int nt = 0; nt < 8; nt++) {
            int n = wn0 + nt * 8 + tg * 2;
            float b0 = bb[n], b1 = bb[n + 1];
#pragma unroll
            for (int mt = 0; mt < 2; mt++) {
                acc[mt][nt][0] = b0; acc[mt][nt][1] = b1;
                acc[mt][nt][2] = b0; acc[mt][nt][3] = b1;
            }
        }

#pragma unroll 1
        for (int kk = 0; kk < 128; kk += 32) {
            __syncthreads();
            for (int i = tid; i < 128 * 8; i += 256) {
                int r = i >> 3, c4 = i & 7;
                float4 v = make_float4(0.f, 0.f, 0.f, 0.f);
                if (row0 + r < NN)
                    v = ((const float4*)x)[(size_t)(row0 + r) * 32 + (kk >> 2) + c4];
                uint32_t* d = (uint32_t*)(xs + r * XS_STRIDE + c4 * 4);
                d[0] = f32_to_tf32(v.x); d[1] = f32_to_tf32(v.y);
                d[2] = f32_to_tf32(v.z); d[3] = f32_to_tf32(v.w);
            }
            for (int i = tid; i < 32 * 32; i += 256) {
                int r = i >> 5, c4 = i & 31;
                float4 v = ((const float4*)W)[(size_t)(kk + r) * 32 + c4];
                uint32_t* d = (uint32_t*)(ws + r * WS_STRIDE + c4 * 4);
                d[0] = f32_to_tf32(v.x); d[1] = f32_to_tf32(v.y);
                d[2] = f32_to_tf32(v.z); d[3] = f32_to_tf32(v.w);
            }
            __syncthreads();

#pragma unroll
            for (int kk2 = 0; kk2 < 32; kk2 += 8) {
                uint32_t afr[2][4];
#pragma unroll
                for (int mt = 0; mt < 2; mt++) {
                    const uint32_t* xr  = (const uint32_t*)(xs + (wm0 + mt * 16 + g) * XS_STRIDE + kk2);
                    const uint32_t* xr8 = (const uint32_t*)(xs + (wm0 + mt * 16 + g + 8) * XS_STRIDE + kk2);
                    afr[mt][0] = xr[tg];
                    afr[mt][1] = xr8[tg];
                    afr[mt][2] = xr[tg + 4];
                    afr[mt][3] = xr8[tg + 4];
                }
#pragma unroll
                for (int nt = 0; nt < 8; nt++) {
                    uint32_t bfr[2];
                    bfr[0] = ((const uint32_t*)(ws + (kk2 + tg) * WS_STRIDE))[wn0 + nt * 8 + g];
                    bfr[1] = ((const uint32_t*)(ws + (kk2 + tg + 4) * WS_STRIDE))[wn0 + nt * 8 + g];
                    mma_tf32(acc[0][nt], afr[0], bfr);
                    mma_tf32(acc[1][nt], afr[1], bfr);
                }
            }
        }

        __syncthreads();
#pragma unroll
        for (int mt = 0; mt < 2; mt++) {
            int rA = row0 + wm0 + mt * 16 + g;
            int rB = rA + 8;
#pragma unroll
            for (int nt = 0; nt < 8; nt++) {
                int n = wn0 + nt * 8 + tg * 2;
                if (rA < NN)
                    *(float2*)(out + (size_t)rA * 128 + n) = make_float2(acc[mt][nt][0], acc[mt][nt][1]);
                if (rB < NN)
                    *(float2*)(out + (size_t)rB * 128 + n) = make_float2(acc[mt][nt][2], acc[mt][nt][3]);
            }
        }
    }
}

// ---------------- fused gather: logits -> exp -> weighted sum -> normalize ----
// one warp per dst node; lane = 4 dims, head = lane/4. No atomics.
__global__ void __launch_bounds__(256) gather_kernel() {
    int node = blockIdx.x * 8 + (threadIdx.x >> 5);
    if (node >= NN) return;
    int lane = threadIdx.x & 31;
    int h = lane >> 2;

    float4 q4 = ((const float4*)g_q)[(size_t)node * 32 + lane];
    int o  = g_off[node];
    int dg = g_deg[node];

    float4 acc = make_float4(0.f, 0.f, 0.f, 0.f);
    float sh = 0.f;

    for (int j = 0; j < dg; j++) {
        int src = g_csr_src[o + j];
        float bias = g_csr_bias[(size_t)(o + j) * HH + h];
        float4 k4 = ((const float4*)g_k)[(size_t)src * 32 + lane];
        float p = q4.x * k4.x + q4.y * k4.y + q4.z * k4.z + q4.w * k4.w;
        p += __shfl_xor_sync(0xffffffffu, p, 1);
        p += __shfl_xor_sync(0xffffffffu, p, 2);
        float ex = __expf(p * 0.25f + bias);
        sh += ex;
        float4 v4 = ((const float4*)g_v)[(size_t)src * 32 + lane];
        acc.x = fmaf(ex, v4.x, acc.x);
        acc.y = fmaf(ex, v4.y, acc.y);
        acc.z = fmaf(ex, v4.z, acc.z);
        acc.w = fmaf(ex, v4.w, acc.w);
    }

    float inv = 1.0f / fmaxf(sh, 1e-6f);
    acc.x *= inv; acc.y *= inv; acc.z *= inv; acc.w *= inv;
    ((float4*)g_agg)[(size_t)node * 32 + lane] = acc;
}

// ---------------- Wo GEMM + GroupNorm epilogue (fp32 SIMT) ---------
__global__ void out_gn_kernel(const float* __restrict__ Wo, const float* __restrict__ bo,
                              const float* __restrict__ gamma, const float* __restrict__ beta,
                              float* __restrict__ out) {
    __shared__ float xs[32 * 128];
    __shared__ float ws[64 * 128];

    const int row0 = blockIdx.x * 32;
    const int tid  = threadIdx.x;

    for (int i = tid; i < 32 * 32; i += 256) {
        int r  = i >> 5;
        int c4 = i & 31;
        float4 val = make_float4(0.f, 0.f, 0.f, 0.f);
        if (row0 + r < NN) val = ((const float4*)g_agg)[(size_t)(row0 + r) * 32 + c4];
        ((float4*)xs)[i] = val;
    }

    const int trow = tid >> 5;
    const int tcol = tid & 31;
    const int r = trow * 4;
    const int c = tcol * 4;

    float acc[4][4];
#pragma unroll
    for (int i = 0; i < 4; i++) {
#pragma unroll
        for (int j = 0; j < 4; j++) acc[i][j] = bo[c + j];
    }

#pragma unroll 1
    for (int kk = 0; kk < 128; kk += 64) {
        __syncthreads();
        for (int i = tid; i < 64 * 32; i += 256)
            ((float4*)ws)[i] = ((const float4*)Wo)[kk * 32 + i];
        __syncthreads();

#pragma unroll 8
        for (int k = 0; k < 64; k++) {
            float4 wv4 = ((float4*)ws)[k * 32 + tcol];
#pragma unroll
            for (int i = 0; i < 4; i++) {
                float a = xs[(r + i) * 128 + kk + k];
                acc[i][0] = fmaf(a, wv4.x, acc[i][0]);
                acc[i][1] = fmaf(a, wv4.y, acc[i][1]);
                acc[i][2] = fmaf(a, wv4.z, acc[i][2]);
                acc[i][3] = fmaf(a, wv4.w, acc[i][3]);
            }
        }
    }

    __syncthreads();
#pragma unroll
    for (int i = 0; i < 4; i++) {
#pragma unroll
        for (int j = 0; j < 4; j++) xs[(r + i) * 128 + c + j] = acc[i][j];
    }
    __syncthreads();

    int srow = tid >> 3;
    int grp  = tid & 7;
    float s = 0.f, s2 = 0.f;
#pragma unroll
    for (int j = 0; j < 16; j++) {
        float v = xs[srow * 128 + grp * 16 + j];
        s += v;
        s2 += v * v;
    }
    float mu  = s * (1.0f / 16.0f);
    float var = s2 * (1.0f / 16.0f) - mu * mu;
    float inv = rsqrtf(var + EPS_GN);

    if (row0 + srow < NN) {
        float* orow = out + (size_t)(row0 + srow) * 128;
#pragma unroll
        for (int j4 = 0; j4 < 4; j4++) {
            int ch0 = grp * 16 + j4 * 4;
            float4 g4 = ((const float4*)gamma)[ch0 >> 2];
            float4 b4 = ((const float4*)beta)[ch0 >> 2];
            float4 o;
            o.x = (xs[srow * 128 + ch0 + 0] - mu) * inv * g4.x + b4.x;
            o.y = (xs[srow * 128 + ch0 + 1] - mu) * inv * g4.y + b4.y;
            o.z = (xs[srow * 128 + ch0 + 2] - mu) * inv * g4.z + b4.z;
            o.w = (xs[srow * 128 + ch0 + 3] - mu) * inv * g4.w + b4.w;
            ((float4*)orow)[ch0 >> 2] = o;
        }
    }
}

// ---------------- launch ----------------
extern "C" void kernel_launch(void* const* d_in, const int* in_sizes, int n_in,
                              void* d_out, int out_size) {
    const float* x         = (const float*)d_in[0];
    const int*   ei        = (const int*)d_in[1];   // int32 (JAX downcasts int64 w/o x64 mode)
    const float* edge_attr = (const float*)d_in[2];
    const float* Wq        = (const float*)d_in[3];
    const float* bq        = (const float*)d_in[4];
    const float* Wk        = (const float*)d_in[5];
    const float* bk        = (const float*)d_in[6];
    const float* Wv        = (const float*)d_in[7];
    const float* bv        = (const float*)d_in[8];
    const float* We        = (const float*)d_in[9];
    const float* be        = (const float*)d_in[10];
    const float* Wo        = (const float*)d_in[11];
    const float* bo        = (const float*)d_in[12];
    const float* gamma     = (const float*)d_in[13];
    const float* beta      = (const float*)d_in[14];
    float* out = (float*)d_out;

    // CSR build
    zero_kernel<<<(NN + 255) / 256, 256>>>();
    hist_kernel<<<(EE + 255) / 256, 256>>>(ei);
    scan_kernel<<<1, 1024>>>();
    scatter_kernel<<<(EE + 255) / 256, 256>>>(ei, edge_attr, We, be);

    // projections
    qkv_tc_kernel<<<(NN + 127) / 128, 256>>>(x, Wq, bq, Wk, bk, Wv, bv);

    // fused attention gather (no atomics)
    gather_kernel<<<(NN + 7) / 8, 256>>>();

    // output projection + GroupNorm
    out_gn_kernel<<<(NN + 31) / 32, 256>>>(Wo, bo, gamma, beta, out);
}

// round 8
// speedup vs baseline: 1.2222x; 1.2156x over previous
#include <cuda_runtime.h>
#include <cuda_bf16.h>
#include <float.h>
#include <math.h>
#include <stdint.h>

#define NN 50000
#define DD 128
#define HH 8
#define HDIM 16
#define EE 800000
#define EDIM 4
#define GROUPS 8
#define EPS_GN 1e-5f

// ---------------- scratch (static device globals; no allocation) ----------------
__device__ __align__(16) float g_q[NN * DD];
__device__ __align__(16) float g_k[NN * DD];
__device__ __align__(16) float g_v[NN * DD];
__device__ __align__(16) float g_agg[NN * DD];
__device__ int g_deg[NN];
__device__ int g_cur[NN];
__device__ int g_off[NN + 1];
__device__ int g_csr_src[EE];
__device__ __align__(16) float g_csr_bias[(size_t)EE * HH];

// ---------------- tf32 helpers ----------------
__device__ __forceinline__ uint32_t f32_to_tf32(float f) {
    uint32_t r;
    asm("cvt.rna.tf32.f32 %0, %1;" : "=r"(r) : "f"(f));
    return r;
}

__device__ __forceinline__ void mma_tf32(float* c, const uint32_t* a, const uint32_t* b) {
    asm volatile(
        "mma.sync.aligned.m16n8k8.row.col.f32.tf32.tf32.f32 "
        "{%0,%1,%2,%3}, {%4,%5,%6,%7}, {%8,%9}, {%0,%1,%2,%3};"
        : "+f"(c[0]), "+f"(c[1]), "+f"(c[2]), "+f"(c[3])
        : "r"(a[0]), "r"(a[1]), "r"(a[2]), "r"(a[3]), "r"(b[0]), "r"(b[1]));
}

// ---------------- CSR build ----------------
__global__ void zero_kernel() {
    int i = blockIdx.x * blockDim.x + threadIdx.x;
    if (i < NN) g_deg[i] = 0;
}

__global__ void hist_kernel(const int* __restrict__ ei) {
    int e = blockIdx.x * blockDim.x + threadIdx.x;
    if (e >= EE) return;
    atomicAdd(&g_deg[ei[EE + e]], 1);
}

// single-block exclusive scan of g_deg -> g_off (and g_cur), warp-shfl two-level
__global__ void scan_kernel() {
    __shared__ int warp_sums[32];
    __shared__ int s_carry;
    const int tid  = threadIdx.x;   // 1024 threads
    const int lane = tid & 31;
    const int wid  = tid >> 5;
    if (tid == 0) s_carry = 0;
    __syncthreads();

    for (int base = 0; base < NN; base += 1024) {
        int idx = base + tid;
        int v = (idx < NN) ? g_deg[idx] : 0;
        int x = v;
#pragma unroll
        for (int s = 1; s < 32; s <<= 1) {
            int t = __shfl_up_sync(0xffffffffu, x, s);
            if (lane >= s) x += t;
        }
        if (lane == 31) warp_sums[wid] = x;
        __syncthreads();
        if (wid == 0) {
            int w = warp_sums[lane];
#pragma unroll
            for (int s = 1; s < 32; s <<= 1) {
                int t = __shfl_up_sync(0xffffffffu, w, s);
                if (lane >= s) w += t;
            }
            warp_sums[lane] = w;
        }
        __syncthreads();
        int incl  = x + (wid > 0 ? warp_sums[wid - 1] : 0);
        int carry = s_carry;
        if (idx < NN) {
            int excl = carry + incl - v;
            g_off[idx] = excl;
            g_cur[idx] = excl;
        }
        __syncthreads();
        if (tid == 1023) s_carry = carry + incl;
        __syncthreads();
    }
    if (tid == 0) g_off[NN] = s_carry;
}

// scatter edges into CSR slots; precompute per-edge head bias in CSR order
__global__ void scatter_kernel(const int* __restrict__ ei,
                               const float* __restrict__ edge_attr,
                               const float* __restrict__ We,
                               const float* __restrict__ be) {
    int e = blockIdx.x * blockDim.x + threadIdx.x;
    if (e >= EE) return;
    int src = ei[e];
    int dst = ei[EE + e];
    int slot = atomicAdd(&g_cur[dst], 1);
    g_csr_src[slot] = src;

    float4 ea = ((const float4*)edge_attr)[e];
    float* bias = &g_csr_bias[(size_t)slot * HH];
#pragma unroll
    for (int h = 0; h < HH; h += 4) {
        float4 o;
        o.x = ea.x * We[0 * HH + h + 0] + ea.y * We[1 * HH + h + 0]
            + ea.z * We[2 * HH + h + 0] + ea.w * We[3 * HH + h + 0] + be[h + 0];
        o.y = ea.x * We[0 * HH + h + 1] + ea.y * We[1 * HH + h + 1]
            + ea.z * We[2 * HH + h + 1] + ea.w * We[3 * HH + h + 1] + be[h + 1];
        o.z = ea.x * We[0 * HH + h + 2] + ea.y * We[1 * HH + h + 2]
            + ea.z * We[2 * HH + h + 2] + ea.w * We[3 * HH + h + 2] + be[h + 2];
        o.w = ea.x * We[0 * HH + h + 3] + ea.y * We[1 * HH + h + 3]
            + ea.z * We[2 * HH + h + 3] + ea.w * We[3 * HH + h + 3] + be[h + 3];
        *(float4*)(bias + h) = o;
    }
}

// ---------------- tf32 tensor-core Q/K/V GEMM ----------------
#define XS_STRIDE 44
#define WS_STRIDE 136

__global__ void __launch_bounds__(256) qkv_tc_kernel(
        const float* __restrict__ x,
        const float* __restrict__ Wq, const float* __restrict__ bq,
        const float* __restrict__ Wk, const float* __restrict__ bk,
        const float* __restrict__ Wv, const float* __restrict__ bv) {
    __shared__ float xs[128 * XS_STRIDE];
    __shared__ float ws[32 * WS_STRIDE];

    const int tid  = threadIdx.x;
    const int wid  = tid >> 5;
    const int lane = tid & 31;
    const int g    = lane >> 2;
    const int tg   = lane & 3;
    const int row0 = blockIdx.x * 128;
    const int wm0  = (wid >> 1) * 32;
    const int wn0  = (wid & 1) * 64;

    const float* Ws[3] = {Wq, Wk, Wv};
    const float* bs[3] = {bq, bk, bv};
    float* outs[3];
    outs[0] = g_q; outs[1] = g_k; outs[2] = g_v;

#pragma unroll 1
    for (int which = 0; which < 3; which++) {
        const float* W = Ws[which];
        const float* bb = bs[which];
        float* out = outs[which];

        float acc[2][8][4];
#pragma unroll
        for (int nt = 0; nt < 8; nt++) {
            int n = wn0 + nt * 8 + tg * 2;
            float b0 = bb[n], b1 = bb[n + 1];
#pragma unroll
            for (int mt = 0; mt < 2; mt++) {
                acc[mt][nt][0] = b0; acc[mt][nt][1] = b1;
                acc[mt][nt][2] = b0; acc[mt][nt][3] = b1;
            }
        }

#pragma unroll 1
        for (int kk = 0; kk < 128; kk += 32) {
            __syncthreads();
            for (int i = tid; i < 128 * 8; i += 256) {
                int r = i >> 3, c4 = i & 7;
                float4 v = make_float4(0.f, 0.f, 0.f, 0.f);
                if (row0 + r < NN)
                    v = ((const float4*)x)[(size_t)(row0 + r) * 32 + (kk >> 2) + c4];
                uint32_t* d = (uint32_t*)(xs + r * XS_STRIDE + c4 * 4);
                d[0] = f32_to_tf32(v.x); d[1] = f32_to_tf32(v.y);
                d[2] = f32_to_tf32(v.z); d[3] = f32_to_tf32(v.w);
            }
            for (int i = tid; i < 32 * 32; i += 256) {
                int r = i >> 5, c4 = i & 31;
                float4 v = ((const float4*)W)[(size_t)(kk + r) * 32 + c4];
                uint32_t* d = (uint32_t*)(ws + r * WS_STRIDE + c4 * 4);
                d[0] = f32_to_tf32(v.x); d[1] = f32_to_tf32(v.y);
                d[2] = f32_to_tf32(v.z); d[3] = f32_to_tf32(v.w);
            }
            __syncthreads();

#pragma unroll
            for (int kk2 = 0; kk2 < 32; kk2 += 8) {
                uint32_t afr[2][4];
#pragma unroll
                for (int mt = 0; mt < 2; mt++) {
                    const uint32_t* xr  = (const uint32_t*)(xs + (wm0 + mt * 16 + g) * XS_STRIDE + kk2);
                    const uint32_t* xr8 = (const uint32_t*)(xs + (wm0 + mt * 16 + g + 8) * XS_STRIDE + kk2);
                    afr[mt][0] = xr[tg];
                    afr[mt][1] = xr8[tg];
                    afr[mt][2] = xr[tg + 4];
                    afr[mt][3] = xr8[tg + 4];
                }
#pragma unroll
                for (int nt = 0; nt < 8; nt++) {
                    uint32_t bfr[2];
                    bfr[0] = ((const uint32_t*)(ws + (kk2 + tg) * WS_STRIDE))[wn0 + nt * 8 + g];
                    bfr[1] = ((const uint32_t*)(ws + (kk2 + tg + 4) * WS_STRIDE))[wn0 + nt * 8 + g];
                    mma_tf32(acc[0][nt], afr[0], bfr);
                    mma_tf32(acc[1][nt], afr[1], bfr);
                }
            }
        }

        __syncthreads();
#pragma unroll
        for (int mt = 0; mt < 2; mt++) {
            int rA = row0 + wm0 + mt * 16 + g;
            int rB = rA + 8;
#pragma unroll
            for (int nt = 0; nt < 8; nt++) {
                int n = wn0 + nt * 8 + tg * 2;
                if (rA < NN)
                    *(float2*)(out + (size_t)rA * 128 + n) = make_float2(acc[mt][nt][0], acc[mt][nt][1]);
                if (rB < NN)
                    *(float2*)(out + (size_t)rB * 128 + n) = make_float2(acc[mt][nt][2], acc[mt][nt][3]);
            }
        }
    }
}

// ---------------- fused gather: batch-4 pipelined, no atomics ----------------
// one warp per dst node; lane = 4 dims, head = lane/4.
__global__ void __launch_bounds__(256) gather_kernel() {
    int node = blockIdx.x * 8 + (threadIdx.x >> 5);
    if (node >= NN) return;
    int lane = threadIdx.x & 31;
    int h = lane >> 2;

    float4 q4 = ((const float4*)g_q)[(size_t)node * 32 + lane];
    int o  = g_off[node];
    int dg = g_deg[node];

    float4 acc = make_float4(0.f, 0.f, 0.f, 0.f);
    float sh = 0.f;

    int j = 0;
    for (; j + 4 <= dg; j += 4) {
        // front-batch all loads: 4 idx + 4 bias + 4 k + 4 v in flight
        int s0 = g_csr_src[o + j + 0];
        int s1 = g_csr_src[o + j + 1];
        int s2 = g_csr_src[o + j + 2];
        int s3 = g_csr_src[o + j + 3];
        float b0 = g_csr_bias[(size_t)(o + j + 0) * HH + h];
        float b1 = g_csr_bias[(size_t)(o + j + 1) * HH + h];
        float b2 = g_csr_bias[(size_t)(o + j + 2) * HH + h];
        float b3 = g_csr_bias[(size_t)(o + j + 3) * HH + h];
        float4 k0 = ((const float4*)g_k)[(size_t)s0 * 32 + lane];
        float4 k1 = ((const float4*)g_k)[(size_t)s1 * 32 + lane];
        float4 k2 = ((const float4*)g_k)[(size_t)s2 * 32 + lane];
        float4 k3 = ((const float4*)g_k)[(size_t)s3 * 32 + lane];
        float4 v0 = ((const float4*)g_v)[(size_t)s0 * 32 + lane];
        float4 v1 = ((const float4*)g_v)[(size_t)s1 * 32 + lane];
        float4 v2 = ((const float4*)g_v)[(size_t)s2 * 32 + lane];
        float4 v3 = ((const float4*)g_v)[(size_t)s3 * 32 + lane];

        float p0 = q4.x * k0.x + q4.y * k0.y + q4.z * k0.z + q4.w * k0.w;
        float p1 = q4.x * k1.x + q4.y * k1.y + q4.z * k1.z + q4.w * k1.w;
        float p2 = q4.x * k2.x + q4.y * k2.y + q4.z * k2.z + q4.w * k2.w;
        float p3 = q4.x * k3.x + q4.y * k3.y + q4.z * k3.z + q4.w * k3.w;
        p0 += __shfl_xor_sync(0xffffffffu, p0, 1);
        p1 += __shfl_xor_sync(0xffffffffu, p1, 1);
        p2 += __shfl_xor_sync(0xffffffffu, p2, 1);
        p3 += __shfl_xor_sync(0xffffffffu, p3, 1);
        p0 += __shfl_xor_sync(0xffffffffu, p0, 2);
        p1 += __shfl_xor_sync(0xffffffffu, p1, 2);
        p2 += __shfl_xor_sync(0xffffffffu, p2, 2);
        p3 += __shfl_xor_sync(0xffffffffu, p3, 2);

        float e0 = __expf(p0 * 0.25f + b0);
        float e1 = __expf(p1 * 0.25f + b1);
        float e2 = __expf(p2 * 0.25f + b2);
        float e3 = __expf(p3 * 0.25f + b3);
        sh += (e0 + e1) + (e2 + e3);

        acc.x = fmaf(e0, v0.x, acc.x); acc.y = fmaf(e0, v0.y, acc.y);
        acc.z = fmaf(e0, v0.z, acc.z); acc.w = fmaf(e0, v0.w, acc.w);
        acc.x = fmaf(e1, v1.x, acc.x); acc.y = fmaf(e1, v1.y, acc.y);
        acc.z = fmaf(e1, v1.z, acc.z); acc.w = fmaf(e1, v1.w, acc.w);
        acc.x = fmaf(e2, v2.x, acc.x); acc.y = fmaf(e2, v2.y, acc.y);
        acc.z = fmaf(e2, v2.z, acc.z); acc.w = fmaf(e2, v2.w, acc.w);
        acc.x = fmaf(e3, v3.x, acc.x); acc.y = fmaf(e3, v3.y, acc.y);
        acc.z = fmaf(e3, v3.z, acc.z); acc.w = fmaf(e3, v3.w, acc.w);
    }

    for (; j < dg; j++) {
        int src = g_csr_src[o + j];
        float bias = g_csr_bias[(size_t)(o + j) * HH + h];
        float4 k4 = ((const float4*)g_k)[(size_t)src * 32 + lane];
        float p = q4.x * k4.x + q4.y * k4.y + q4.z * k4.z + q4.w * k4.w;
        p += __shfl_xor_sync(0xffffffffu, p, 1);
        p += __shfl_xor_sync(0xffffffffu, p, 2);
        float ex = __expf(p * 0.25f + bias);
        sh += ex;
        float4 v4 = ((const float4*)g_v)[(size_t)src * 32 + lane];
        acc.x = fmaf(ex, v4.x, acc.x);
        acc.y = fmaf(ex, v4.y, acc.y);
        acc.z = fmaf(ex, v4.z, acc.z);
        acc.w = fmaf(ex, v4.w, acc.w);
    }

    float inv = 1.0f / fmaxf(sh, 1e-6f);
    acc.x *= inv; acc.y *= inv; acc.z *= inv; acc.w *= inv;
    ((float4*)g_agg)[(size_t)node * 32 + lane] = acc;
}

// ---------------- Wo GEMM + GroupNorm epilogue (fp32 SIMT) ---------
__global__ void out_gn_kernel(const float* __restrict__ Wo, const float* __restrict__ bo,
                              const float* __restrict__ gamma, const float* __restrict__ beta,
                              float* __restrict__ out) {
    __shared__ float xs[32 * 128];
    __shared__ float ws[64 * 128];

    const int row0 = blockIdx.x * 32;
    const int tid  = threadIdx.x;

    for (int i = tid; i < 32 * 32; i += 256) {
        int r  = i >> 5;
        int c4 = i & 31;
        float4 val = make_float4(0.f, 0.f, 0.f, 0.f);
        if (row0 + r < NN) val = ((const float4*)g_agg)[(size_t)(row0 + r) * 32 + c4];
        ((float4*)xs)[i] = val;
    }

    const int trow = tid >> 5;
    const int tcol = tid & 31;
    const int r = trow * 4;
    const int c = tcol * 4;

    float acc[4][4];
#pragma unroll
    for (int i = 0; i < 4; i++) {
#pragma unroll
        for (int j = 0; j < 4; j++) acc[i][j] = bo[c + j];
    }

#pragma unroll 1
    for (int kk = 0; kk < 128; kk += 64) {
        __syncthreads();
        for (int i = tid; i < 64 * 32; i += 256)
            ((float4*)ws)[i] = ((const float4*)Wo)[kk * 32 + i];
        __syncthreads();

#pragma unroll 8
        for (int k = 0; k < 64; k++) {
            float4 wv4 = ((float4*)ws)[k * 32 + tcol];
#pragma unroll
            for (int i = 0; i < 4; i++) {
                float a = xs[(r + i) * 128 + kk + k];
                acc[i][0] = fmaf(a, wv4.x, acc[i][0]);
                acc[i][1] = fmaf(a, wv4.y, acc[i][1]);
                acc[i][2] = fmaf(a, wv4.z, acc[i][2]);
                acc[i][3] = fmaf(a, wv4.w, acc[i][3]);
            }
        }
    }

    __syncthreads();
#pragma unroll
    for (int i = 0; i < 4; i++) {
#pragma unroll
        for (int j = 0; j < 4; j++) xs[(r + i) * 128 + c + j] = acc[i][j];
    }
    __syncthreads();

    int srow = tid >> 3;
    int grp  = tid & 7;
    float s = 0.f, s2 = 0.f;
#pragma unroll
    for (int j = 0; j < 16; j++) {
        float v = xs[srow * 128 + grp * 16 + j];
        s += v;
        s2 += v * v;
    }
    float mu  = s * (1.0f / 16.0f);
    float var = s2 * (1.0f / 16.0f) - mu * mu;
    float inv = rsqrtf(var + EPS_GN);

    if (row0 + srow < NN) {
        float* orow = out + (size_t)(row0 + srow) * 128;
#pragma unroll
        for (int j4 = 0; j4 < 4; j4++) {
            int ch0 = grp * 16 + j4 * 4;
            float4 g4 = ((const float4*)gamma)[ch0 >> 2];
            float4 b4 = ((const float4*)beta)[ch0 >> 2];
            float4 o;
            o.x = (xs[srow * 128 + ch0 + 0] - mu) * inv * g4.x + b4.x;
            o.y = (xs[srow * 128 + ch0 + 1] - mu) * inv * g4.y + b4.y;
            o.z = (xs[srow * 128 + ch0 + 2] - mu) * inv * g4.z + b4.z;
            o.w = (xs[srow * 128 + ch0 + 3] - mu) * inv * g4.w + b4.w;
            ((float4*)orow)[ch0 >> 2] = o;
        }
    }
}

// ---------------- launch ----------------
extern "C" void kernel_launch(void* const* d_in, const int* in_sizes, int n_in,
                              void* d_out, int out_size) {
    const float* x         = (const float*)d_in[0];
    const int*   ei        = (const int*)d_in[1];   // int32 (JAX downcasts int64 w/o x64 mode)
    const float* edge_attr = (const float*)d_in[2];
    const float* Wq        = (const float*)d_in[3];
    const float* bq        = (const float*)d_in[4];
    const float* Wk        = (const float*)d_in[5];
    const float* bk        = (const float*)d_in[6];
    const float* Wv        = (const float*)d_in[7];
    const float* bv        = (const float*)d_in[8];
    const float* We        = (const float*)d_in[9];
    const float* be        = (const float*)d_in[10];
    const float* Wo        = (const float*)d_in[11];
    const float* bo        = (const float*)d_in[12];
    const float* gamma     = (const float*)d_in[13];
    const float* beta      = (const float*)d_in[14];
    float* out = (float*)d_out;

    // CSR build
    zero_kernel<<<(NN + 255) / 256, 256>>>();
    hist_kernel<<<(EE + 255) / 256, 256>>>(ei);
    scan_kernel<<<1, 1024>>>();
    scatter_kernel<<<(EE + 255) / 256, 256>>>(ei, edge_attr, We, be);

    // projections
    qkv_tc_kernel<<<(NN + 127) / 128, 256>>>(x, Wq, bq, Wk, bk, Wv, bv);

    // fused attention gather (no atomics, batch-4 pipelined)
    gather_kernel<<<(NN + 7) / 8, 256>>>();

    // output projection + GroupNorm
    out_gn_kernel<<<(NN + 31) / 32, 256>>>(Wo, bo, gamma, beta, out);
}

// round 10
// speedup vs baseline: 1.2357x; 1.0110x over previous
#include <cuda_runtime.h>
#include <cuda_bf16.h>
#include <float.h>
#include <math.h>
#include <stdint.h>

#define NN 50000
#define DD 128
#define HH 8
#define HDIM 16
#define EE 800000
#define EDIM 4
#define GROUPS 8
#define EPS_GN 1e-5f

// ---------------- scratch (static device globals; no allocation) ----------------
__device__ __align__(16) float g_q[NN * DD];
__device__ __align__(16) float g_k[NN * DD];
__device__ __align__(16) float g_v[NN * DD];
__device__ __align__(16) float g_agg[NN * DD];
__device__ int g_deg[NN];
__device__ int g_cur[NN];
__device__ int g_off[NN + 1];
__device__ int g_csr_src[EE];
__device__ __align__(16) float4 g_csr_ea[EE];

// ---------------- tf32 helpers ----------------
__device__ __forceinline__ uint32_t f32_to_tf32(float f) {
    uint32_t r;
    asm("cvt.rna.tf32.f32 %0, %1;" : "=r"(r) : "f"(f));
    return r;
}

__device__ __forceinline__ void mma_tf32(float* c, const uint32_t* a, const uint32_t* b) {
    asm volatile(
        "mma.sync.aligned.m16n8k8.row.col.f32.tf32.tf32.f32 "
        "{%0,%1,%2,%3}, {%4,%5,%6,%7}, {%8,%9}, {%0,%1,%2,%3};"
        : "+f"(c[0]), "+f"(c[1]), "+f"(c[2]), "+f"(c[3])
        : "r"(a[0]), "r"(a[1]), "r"(a[2]), "r"(a[3]), "r"(b[0]), "r"(b[1]));
}

// ---------------- CSR build ----------------
__global__ void zero_kernel() {
    int i = blockIdx.x * blockDim.x + threadIdx.x;
    if (i < NN) g_deg[i] = 0;
}

__global__ void hist_kernel(const int* __restrict__ ei) {
    int e = blockIdx.x * blockDim.x + threadIdx.x;
    if (e >= EE) return;
    atomicAdd(&g_deg[ei[EE + e]], 1);
}

// single-block exclusive scan of g_deg -> g_off (and g_cur), warp-shfl two-level
__global__ void scan_kernel() {
    __shared__ int warp_sums[32];
    __shared__ int s_carry;
    const int tid  = threadIdx.x;   // 1024 threads
    const int lane = tid & 31;
    const int wid  = tid >> 5;
    if (tid == 0) s_carry = 0;
    __syncthreads();

    for (int base = 0; base < NN; base += 1024) {
        int idx = base + tid;
        int v = (idx < NN) ? g_deg[idx] : 0;
        int x = v;
#pragma unroll
        for (int s = 1; s < 32; s <<= 1) {
            int t = __shfl_up_sync(0xffffffffu, x, s);
            if (lane >= s) x += t;
        }
        if (lane == 31) warp_sums[wid] = x;
        __syncthreads();
        if (wid == 0) {
            int w = warp_sums[lane];
#pragma unroll
            for (int s = 1; s < 32; s <<= 1) {
                int t = __shfl_up_sync(0xffffffffu, w, s);
                if (lane >= s) w += t;
            }
            warp_sums[lane] = w;
        }
        __syncthreads();
        int incl  = x + (wid > 0 ? warp_sums[wid - 1] : 0);
        int carry = s_carry;
        if (idx < NN) {
            int excl = carry + incl - v;
            g_off[idx] = excl;
            g_cur[idx] = excl;
        }
        __syncthreads();
        if (tid == 1023) s_carry = carry + incl;
        __syncthreads();
    }
    if (tid == 0) g_off[NN] = s_carry;
}

// scatter edges into CSR slots (2 edges/thread, front-batched loads)
__global__ void scatter_kernel(const int* __restrict__ ei,
                               const float* __restrict__ edge_attr) {
    int t = blockIdx.x * blockDim.x + threadIdx.x;
    int e0 = t;
    int e1 = t + EE / 2;
    if (e0 >= EE / 2) return;

    int src0 = ei[e0];
    int src1 = ei[e1];
    int dst0 = ei[EE + e0];
    int dst1 = ei[EE + e1];
    float4 ea0 = ((const float4*)edge_attr)[e0];
    float4 ea1 = ((const float4*)edge_attr)[e1];

    int slot0 = atomicAdd(&g_cur[dst0], 1);
    int slot1 = atomicAdd(&g_cur[dst1], 1);
    g_csr_src[slot0] = src0;
    g_csr_src[slot1] = src1;
    g_csr_ea[slot0] = ea0;
    g_csr_ea[slot1] = ea1;
}

// ---------------- tf32 tensor-core Q/K/V GEMM ----------------
#define XS_STRIDE 44
#define WS_STRIDE 136

__global__ void __launch_bounds__(256) qkv_tc_kernel(
        const float* __restrict__ x,
        const float* __restrict__ Wq, const float* __restrict__ bq,
        const float* __restrict__ Wk, const float* __restrict__ bk,
        const float* __restrict__ Wv, const float* __restrict__ bv) {
    __shared__ float xs[128 * XS_STRIDE];
    __shared__ float ws[32 * WS_STRIDE];

    const int tid  = threadIdx.x;
    const int wid  = tid >> 5;
    const int lane = tid & 31;
    const int g    = lane >> 2;
    const int tg   = lane & 3;
    const int row0 = blockIdx.x * 128;
    const int wm0  = (wid >> 1) * 32;
    const int wn0  = (wid & 1) * 64;

    const float* Ws[3] = {Wq, Wk, Wv};
    const float* bs[3] = {bq, bk, bv};
    float* outs[3];
    outs[0] = g_q; outs[1] = g_k; outs[2] = g_v;

#pragma unroll 1
    for (int which = 0; which < 3; which++) {
        const float* W = Ws[which];
        const float* bb = bs[which];
        float* out = outs[which];

        float acc[2][8][4];
#pragma unroll
        for (int nt = 0; nt < 8; nt++) {
            int n = wn0 + nt * 8 + tg * 2;
            float b0 = bb[n], b1 = bb[n + 1];
#pragma unroll
            for (int mt = 0; mt < 2; mt++) {
                acc[mt][nt][0] = b0; acc[mt][nt][1] = b1;
                acc[mt][nt][2] = b0; acc[mt][nt][3] = b1;
            }
        }

#pragma unroll 1
        for (int kk = 0; kk < 128; kk += 32) {
            __syncthreads();
            for (int i = tid; i < 128 * 8; i += 256) {
                int r = i >> 3, c4 = i & 7;
                float4 v = make_float4(0.f, 0.f, 0.f, 0.f);
                if (row0 + r < NN)
                    v = ((const float4*)x)[(size_t)(row0 + r) * 32 + (kk >> 2) + c4];
                uint32_t* d = (uint32_t*)(xs + r * XS_STRIDE + c4 * 4);
                d[0] = f32_to_tf32(v.x); d[1] = f32_to_tf32(v.y);
                d[2] = f32_to_tf32(v.z); d[3] = f32_to_tf32(v.w);
            }
            for (int i = tid; i < 32 * 32; i += 256) {
                int r = i >> 5, c4 = i & 31;
                float4 v = ((const float4*)W)[(size_t)(kk + r) * 32 + c4];
                uint32_t* d = (uint32_t*)(ws + r * WS_STRIDE + c4 * 4);
                d[0] = f32_to_tf32(v.x); d[1] = f32_to_tf32(v.y);
                d[2] = f32_to_tf32(v.z); d[3] = f32_to_tf32(v.w);
            }
            __syncthreads();

#pragma unroll
            for (int kk2 = 0; kk2 < 32; kk2 += 8) {
                uint32_t afr[2][4];
#pragma unroll
                for (int mt = 0; mt < 2; mt++) {
                    const uint32_t* xr  = (const uint32_t*)(xs + (wm0 + mt * 16 + g) * XS_STRIDE + kk2);
                    const uint32_t* xr8 = (const uint32_t*)(xs + (wm0 + mt * 16 + g + 8) * XS_STRIDE + kk2);
                    afr[mt][0] = xr[tg];
                    afr[mt][1] = xr8[tg];
                    afr[mt][2] = xr[tg + 4];
                    afr[mt][3] = xr8[tg + 4];
                }
#pragma unroll
                for (int nt = 0; nt < 8; nt++) {
                    uint32_t bfr[2];
                    bfr[0] = ((const uint32_t*)(ws + (kk2 + tg) * WS_STRIDE))[wn0 + nt * 8 + g];
                    bfr[1] = ((const uint32_t*)(ws + (kk2 + tg + 4) * WS_STRIDE))[wn0 + nt * 8 + g];
                    mma_tf32(acc[0][nt], afr[0], bfr);
                    mma_tf32(acc[1][nt], afr[1], bfr);
                }
            }
        }

        __syncthreads();
#pragma unroll
        for (int mt = 0; mt < 2; mt++) {
            int rA = row0 + wm0 + mt * 16 + g;
            int rB = rA + 8;
#pragma unroll
            for (int nt = 0; nt < 8; nt++) {
                int n = wn0 + nt * 8 + tg * 2;
                if (rA < NN)
                    *(float2*)(out + (size_t)rA * 128 + n) = make_float2(acc[mt][nt][0], acc[mt][nt][1]);
                if (rB < NN)
                    *(float2*)(out + (size_t)rB * 128 + n) = make_float2(acc[mt][nt][2], acc[mt][nt][3]);
            }
        }
    }
}

// ---------------- fused gather: batch-4 pipelined, inline bias, no atomics ----
// one warp per dst node; lane = 4 dims, head = lane/4.
__global__ void __launch_bounds__(256) gather_kernel(const float* __restrict__ We,
                                                     const float* __restrict__ be) {
    int node = blockIdx.x * 8 + (threadIdx.x >> 5);
    if (node >= NN) return;
    int lane = threadIdx.x & 31;
    int h = lane >> 2;

    // per-lane We column + bias for this head
    float we0 = We[0 * HH + h], we1 = We[1 * HH + h];
    float we2 = We[2 * HH + h], we3 = We[3 * HH + h];
    float beh = be[h];

    float4 q4 = ((const float4*)g_q)[(size_t)node * 32 + lane];
    int o  = g_off[node];
    int dg = g_deg[node];

    float4 acc = make_float4(0.f, 0.f, 0.f, 0.f);
    float sh = 0.f;

    int j = 0;
    for (; j + 4 <= dg; j += 4) {
        int s0 = g_csr_src[o + j + 0];
        int s1 = g_csr_src[o + j + 1];
        int s2 = g_csr_src[o + j + 2];
        int s3 = g_csr_src[o + j + 3];
        float4 a0 = g_csr_ea[o + j + 0];
        float4 a1 = g_csr_ea[o + j + 1];
        float4 a2 = g_csr_ea[o + j + 2];
        float4 a3 = g_csr_ea[o + j + 3];
        float4 k0 = ((const float4*)g_k)[(size_t)s0 * 32 + lane];
        float4 k1 = ((const float4*)g_k)[(size_t)s1 * 32 + lane];
        float4 k2 = ((const float4*)g_k)[(size_t)s2 * 32 + lane];
        float4 k3 = ((const float4*)g_k)[(size_t)s3 * 32 + lane];
        float4 v0 = ((const float4*)g_v)[(size_t)s0 * 32 + lane];
        float4 v1 = ((const float4*)g_v)[(size_t)s1 * 32 + lane];
        float4 v2 = ((const float4*)g_v)[(size_t)s2 * 32 + lane];
        float4 v3 = ((const float4*)g_v)[(size_t)s3 * 32 + lane];

        float p0 = q4.x * k0.x + q4.y * k0.y + q4.z * k0.z + q4.w * k0.w;
        float p1 = q4.x * k1.x + q4.y * k1.y + q4.z * k1.z + q4.w * k1.w;
        float p2 = q4.x * k2.x + q4.y * k2.y + q4.z * k2.z + q4.w * k2.w;
        float p3 = q4.x * k3.x + q4.y * k3.y + q4.z * k3.z + q4.w * k3.w;
        p0 += __shfl_xor_sync(0xffffffffu, p0, 1);
        p1 += __shfl_xor_sync(0xffffffffu, p1, 1);
        p2 += __shfl_xor_sync(0xffffffffu, p2, 1);
        p3 += __shfl_xor_sync(0xffffffffu, p3, 1);
        p0 += __shfl_xor_sync(0xffffffffu, p0, 2);
        p1 += __shfl_xor_sync(0xffffffffu, p1, 2);
        p2 += __shfl_xor_sync(0xffffffffu, p2, 2);
        p3 += __shfl_xor_sync(0xffffffffu, p3, 2);

        float b0 = a0.x * we0 + a0.y * we1 + a0.z * we2 + a0.w * we3 + beh;
        float b1 = a1.x * we0 + a1.y * we1 + a1.z * we2 + a1.w * we3 + beh;
        float b2 = a2.x * we0 + a2.y * we1 + a2.z * we2 + a2.w * we3 + beh;
        float b3 = a3.x * we0 + a3.y * we1 + a3.z * we2 + a3.w * we3 + beh;

        float e0 = __expf(p0 * 0.25f + b0);
        float e1 = __expf(p1 * 0.25f + b1);
        float e2 = __expf(p2 * 0.25f + b2);
        float e3 = __expf(p3 * 0.25f + b3);
        sh += (e0 + e1) + (e2 + e3);

        acc.x = fmaf(e0, v0.x, acc.x); acc.y = fmaf(e0, v0.y, acc.y);
        acc.z = fmaf(e0, v0.z, acc.z); acc.w = fmaf(e0, v0.w, acc.w);
        acc.x = fmaf(e1, v1.x, acc.x); acc.y = fmaf(e1, v1.y, acc.y);
        acc.z = fmaf(e1, v1.z, acc.z); acc.w = fmaf(e1, v1.w, acc.w);
        acc.x = fmaf(e2, v2.x, acc.x); acc.y = fmaf(e2, v2.y, acc.y);
        acc.z = fmaf(e2, v2.z, acc.z); acc.w = fmaf(e2, v2.w, acc.w);
        acc.x = fmaf(e3, v3.x, acc.x); acc.y = fmaf(e3, v3.y, acc.y);
        acc.z = fmaf(e3, v3.z, acc.z); acc.w = fmaf(e3, v3.w, acc.w);
    }

    for (; j < dg; j++) {
        int src = g_csr_src[o + j];
        float4 a0 = g_csr_ea[o + j];
        float4 k4 = ((const float4*)g_k)[(size_t)src * 32 + lane];
        float p = q4.x * k4.x + q4.y * k4.y + q4.z * k4.z + q4.w * k4.w;
        p += __shfl_xor_sync(0xffffffffu, p, 1);
        p += __shfl_xor_sync(0xffffffffu, p, 2);
        float bias = a0.x * we0 + a0.y * we1 + a0.z * we2 + a0.w * we3 + beh;
        float ex = __expf(p * 0.25f + bias);
        sh += ex;
        float4 v4 = ((const float4*)g_v)[(size_t)src * 32 + lane];
        acc.x = fmaf(ex, v4.x, acc.x);
        acc.y = fmaf(ex, v4.y, acc.y);
        acc.z = fmaf(ex, v4.z, acc.z);
        acc.w = fmaf(ex, v4.w, acc.w);
    }

    float inv = 1.0f / fmaxf(sh, 1e-6f);
    acc.x *= inv; acc.y *= inv; acc.z *= inv; acc.w *= inv;
    ((float4*)g_agg)[(size_t)node * 32 + lane] = acc;
}

// ---------------- Wo GEMM (tf32 TC) + register-resident GroupNorm ------------
// Same tile/layout as qkv_tc. Each 16-channel group lives in one warp's 4-lane
// tg-group -> group stats via shfl_xor(1),shfl_xor(2). No smem epilogue.
__global__ void __launch_bounds__(256) out_gn_tc_kernel(
        const float* __restrict__ Wo, const float* __restrict__ bo,
        const float* __restrict__ gamma, const float* __restrict__ beta,
        float* __restrict__ out) {
    __shared__ float xs[128 * XS_STRIDE];
    __shared__ float ws[32 * WS_STRIDE];

    const int tid  = threadIdx.x;
    const int wid  = tid >> 5;
    const int lane = tid & 31;
    const int g    = lane >> 2;
    const int tg   = lane & 3;
    const int row0 = blockIdx.x * 128;
    const int wm0  = (wid >> 1) * 32;
    const int wn0  = (wid & 1) * 64;

    float acc[2][8][4];
#pragma unroll
    for (int nt = 0; nt < 8; nt++) {
        int n = wn0 + nt * 8 + tg * 2;
        float b0 = bo[n], b1 = bo[n + 1];
#pragma unroll
        for (int mt = 0; mt < 2; mt++) {
            acc[mt][nt][0] = b0; acc[mt][nt][1] = b1;
            acc[mt][nt][2] = b0; acc[mt][nt][3] = b1;
        }
    }

#pragma unroll 1
    for (int kk = 0; kk < 128; kk += 32) {
        __syncthreads();
        for (int i = tid; i < 128 * 8; i += 256) {
            int r = i >> 3, c4 = i & 7;
            float4 v = make_float4(0.f, 0.f, 0.f, 0.f);
            if (row0 + r < NN)
                v = ((const float4*)g_agg)[(size_t)(row0 + r) * 32 + (kk >> 2) + c4];
            uint32_t* d = (uint32_t*)(xs + r * XS_STRIDE + c4 * 4);
            d[0] = f32_to_tf32(v.x); d[1] = f32_to_tf32(v.y);
            d[2] = f32_to_tf32(v.z); d[3] = f32_to_tf32(v.w);
        }
        for (int i = tid; i < 32 * 32; i += 256) {
            int r = i >> 5, c4 = i & 31;
            float4 v = ((const float4*)Wo)[(size_t)(kk + r) * 32 + c4];
            uint32_t* d = (uint32_t*)(ws + r * WS_STRIDE + c4 * 4);
            d[0] = f32_to_tf32(v.x); d[1] = f32_to_tf32(v.y);
            d[2] = f32_to_tf32(v.z); d[3] = f32_to_tf32(v.w);
        }
        __syncthreads();

#pragma unroll
        for (int kk2 = 0; kk2 < 32; kk2 += 8) {
            uint32_t afr[2][4];
#pragma unroll
            for (int mt = 0; mt < 2; mt++) {
                const uint32_t* xr  = (const uint32_t*)(xs + (wm0 + mt * 16 + g) * XS_STRIDE + kk2);
                const uint32_t* xr8 = (const uint32_t*)(xs + (wm0 + mt * 16 + g + 8) * XS_STRIDE + kk2);
                afr[mt][0] = xr[tg];
                afr[mt][1] = xr8[tg];
                afr[mt][2] = xr[tg + 4];
                afr[mt][3] = xr8[tg + 4];
            }
#pragma unroll
            for (int nt = 0; nt < 8; nt++) {
                uint32_t bfr[2];
                bfr[0] = ((const uint32_t*)(ws + (kk2 + tg) * WS_STRIDE))[wn0 + nt * 8 + g];
                bfr[1] = ((const uint32_t*)(ws + (kk2 + tg + 4) * WS_STRIDE))[wn0 + nt * 8 + g];
                mma_tf32(acc[0][nt], afr[0], bfr);
                mma_tf32(acc[1][nt], afr[1], bfr);
            }
        }
    }

    // GroupNorm epilogue, fully in registers.
    // Row rA = row0+wm0+mt*16+g holds acc[mt][nt][0..1]; rB=rA+8 holds [2..3].
    // Group gi (cols wn0+gi*16 .. +15) = nt in {2gi, 2gi+1} x tg(0..3).
#pragma unroll
    for (int mt = 0; mt < 2; mt++) {
        int rA = row0 + wm0 + mt * 16 + g;
        int rB = rA + 8;
#pragma unroll
        for (int gi = 0; gi < 4; gi++) {
            int nt0 = 2 * gi, nt1 = 2 * gi + 1;
            // rA stats
            float sA = acc[mt][nt0][0] + acc[mt][nt0][1] + acc[mt][nt1][0] + acc[mt][nt1][1];
            float s2A = acc[mt][nt0][0] * acc[mt][nt0][0] + acc[mt][nt0][1] * acc[mt][nt0][1]
                      + acc[mt][nt1][0] * acc[mt][nt1][0] + acc[mt][nt1][1] * acc[mt][nt1][1];
            // rB stats
            float sB = acc[mt][nt0][2] + acc[mt][nt0][3] + acc[mt][nt1][2] + acc[mt][nt1][3];
            float s2B = acc[mt][nt0][2] * acc[mt][nt0][2] + acc[mt][nt0][3] * acc[mt][nt0][3]
                      + acc[mt][nt1][2] * acc[mt][nt1][2] + acc[mt][nt1][3] * acc[mt][nt1][3];
            sA  += __shfl_xor_sync(0xffffffffu, sA, 1);
            s2A += __shfl_xor_sync(0xffffffffu, s2A, 1);
            sB  += __shfl_xor_sync(0xffffffffu, sB, 1);
            s2B += __shfl_xor_sync(0xffffffffu, s2B, 1);
            sA  += __shfl_xor_sync(0xffffffffu, sA, 2);
            s2A += __shfl_xor_sync(0xffffffffu, s2A, 2);
            sB  += __shfl_xor_sync(0xffffffffu, sB, 2);
            s2B += __shfl_xor_sync(0xffffffffu, s2B, 2);

            float muA = sA * (1.0f / 16.0f);
            float varA = s2A * (1.0f / 16.0f) - muA * muA;
            float invA = rsqrtf(varA + EPS_GN);
            float muB = sB * (1.0f / 16.0f);
            float varB = s2B * (1.0f / 16.0f) - muB * muB;
            float invB = rsqrtf(varB + EPS_GN);

            int n0 = wn0 + nt0 * 8 + tg * 2;
            int n1 = wn0 + nt1 * 8 + tg * 2;
            float ga0 = gamma[n0], ga1 = gamma[n0 + 1];
            float ga2 = gamma[n1], ga3 = gamma[n1 + 1];
            float bt0 = beta[n0], bt1 = beta[n0 + 1];
            float bt2 = beta[n1], bt3 = beta[n1 + 1];

            if (rA < NN) {
                *(float2*)(out + (size_t)rA * 128 + n0) = make_float2(
                    (acc[mt][nt0][0] - muA) * invA * ga0 + bt0,
                    (acc[mt][nt0][1] - muA) * invA * ga1 + bt1);
                *(float2*)(out + (size_t)rA * 128 + n1) = make_float2(
                    (acc[mt][nt1][0] - muA) * invA * ga2 + bt2,
                    (acc[mt][nt1][1] - muA) * invA * ga3 + bt3);
            }
            if (rB < NN) {
                *(float2*)(out + (size_t)rB * 128 + n0) = make_float2(
                    (acc[mt][nt0][2] - muB) * invB * ga0 + bt0,
                    (acc[mt][nt0][3] - muB) * invB * ga1 + bt1);
                *(float2*)(out + (size_t)rB * 128 + n1) = make_float2(
                    (acc[mt][nt1][2] - muB) * invB * ga2 + bt2,
                    (acc[mt][nt1][3] - muB) * invB * ga3 + bt3);
            }
        }
    }
}

// ---------------- launch ----------------
extern "C" void kernel_launch(void* const* d_in, const int* in_sizes, int n_in,
                              void* d_out, int out_size) {
    const float* x         = (const float*)d_in[0];
    const int*   ei        = (const int*)d_in[1];   // int32 (JAX downcasts int64 w/o x64 mode)
    const float* edge_attr = (const float*)d_in[2];
    const float* Wq        = (const float*)d_in[3];
    const float* bq        = (const float*)d_in[4];
    const float* Wk        = (const float*)d_in[5];
    const float* bk        = (const float*)d_in[6];
    const float* Wv        = (const float*)d_in[7];
    const float* bv        = (const float*)d_in[8];
    const float* We        = (const float*)d_in[9];
    const float* be        = (const float*)d_in[10];
    const float* Wo        = (const float*)d_in[11];
    const float* bo        = (const float*)d_in[12];
    const float* gamma     = (const float*)d_in[13];
    const float* beta      = (const float*)d_in[14];
    float* out = (float*)d_out;

    // CSR build
    zero_kernel<<<(NN + 255) / 256, 256>>>();
    hist_kernel<<<(EE + 255) / 256, 256>>>(ei);
    scan_kernel<<<1, 1024>>>();
    scatter_kernel<<<(EE / 2 + 255) / 256, 256>>>(ei, edge_attr);

    // projections
    qkv_tc_kernel<<<(NN + 127) / 128, 256>>>(x, Wq, bq, Wk, bk, Wv, bv);

    // fused attention gather (no atomics, batch-4 pipelined, inline bias)
    gather_kernel<<<(NN + 7) / 8, 256>>>(We, be);

    // output projection (tf32 TC) + register GroupNorm
    out_gn_tc_kernel<<<(NN + 127) / 128, 256>>>(Wo, bo, gamma, beta, out);
}

// round 12
// speedup vs baseline: 1.2619x; 1.0212x over previous
#include <cuda_runtime.h>
#include <cuda_bf16.h>
#include <float.h>
#include <math.h>
#include <stdint.h>

#define NN 50000
#define DD 128
#define HH 8
#define HDIM 16
#define EE 800000
#define EDIM 4
#define GROUPS 8
#define EPS_GN 1e-5f

// ---------------- scratch (static device globals; no allocation) ----------------
__device__ __align__(16) float g_q[NN * DD];
__device__ __align__(16) float g_k[NN * DD];
__device__ __align__(16) float g_v[NN * DD];
__device__ __align__(16) float g_agg[NN * DD];
__device__ int g_deg[NN];
__device__ int g_cur[NN];
__device__ int g_off[NN + 1];
__device__ int g_csr_src[EE];
__device__ __align__(16) float4 g_csr_ea[EE];

// ---------------- tf32 helpers ----------------
__device__ __forceinline__ uint32_t f32_to_tf32(float f) {
    uint32_t r;
    asm("cvt.rna.tf32.f32 %0, %1;" : "=r"(r) : "f"(f));
    return r;
}

__device__ __forceinline__ void mma_tf32(float* c, const uint32_t* a, const uint32_t* b) {
    asm volatile(
        "mma.sync.aligned.m16n8k8.row.col.f32.tf32.tf32.f32 "
        "{%0,%1,%2,%3}, {%4,%5,%6,%7}, {%8,%9}, {%0,%1,%2,%3};"
        : "+f"(c[0]), "+f"(c[1]), "+f"(c[2]), "+f"(c[3])
        : "r"(a[0]), "r"(a[1]), "r"(a[2]), "r"(a[3]), "r"(b[0]), "r"(b[1]));
}

// ---------------- CSR build ----------------
__global__ void zero_kernel() {
    int i = blockIdx.x * blockDim.x + threadIdx.x;
    if (i < NN) g_deg[i] = 0;
}

__global__ void hist_kernel(const int* __restrict__ ei) {
    int e = blockIdx.x * blockDim.x + threadIdx.x;
    if (e >= EE) return;
    atomicAdd(&g_deg[ei[EE + e]], 1);
}

// single-block exclusive scan of g_deg -> g_off (and g_cur), warp-shfl two-level
__global__ void scan_kernel() {
    __shared__ int warp_sums[32];
    __shared__ int s_carry;
    const int tid  = threadIdx.x;   // 1024 threads
    const int lane = tid & 31;
    const int wid  = tid >> 5;
    if (tid == 0) s_carry = 0;
    __syncthreads();

    for (int base = 0; base < NN; base += 1024) {
        int idx = base + tid;
        int v = (idx < NN) ? g_deg[idx] : 0;
        int x = v;
#pragma unroll
        for (int s = 1; s < 32; s <<= 1) {
            int t = __shfl_up_sync(0xffffffffu, x, s);
            if (lane >= s) x += t;
        }
        if (lane == 31) warp_sums[wid] = x;
        __syncthreads();
        if (wid == 0) {
            int w = warp_sums[lane];
#pragma unroll
            for (int s = 1; s < 32; s <<= 1) {
                int t = __shfl_up_sync(0xffffffffu, w, s);
                if (lane >= s) w += t;
            }
            warp_sums[lane] = w;
        }
        __syncthreads();
        int incl  = x + (wid > 0 ? warp_sums[wid - 1] : 0);
        int carry = s_carry;
        if (idx < NN) {
            int excl = carry + incl - v;
            g_off[idx] = excl;
            g_cur[idx] = excl;
        }
        __syncthreads();
        if (tid == 1023) s_carry = carry + incl;
        __syncthreads();
    }
    if (tid == 0) g_off[NN] = s_carry;
}

// scatter edges into CSR slots (2 edges/thread, front-batched loads)
__global__ void scatter_kernel(const int* __restrict__ ei,
                               const float* __restrict__ edge_attr) {
    int t = blockIdx.x * blockDim.x + threadIdx.x;
    int e0 = t;
    int e1 = t + EE / 2;
    if (e0 >= EE / 2) return;

    int src0 = ei[e0];
    int src1 = ei[e1];
    int dst0 = ei[EE + e0];
    int dst1 = ei[EE + e1];
    float4 ea0 = ((const float4*)edge_attr)[e0];
    float4 ea1 = ((const float4*)edge_attr)[e1];

    int slot0 = atomicAdd(&g_cur[dst0], 1);
    int slot1 = atomicAdd(&g_cur[dst1], 1);
    g_csr_src[slot0] = src0;
    g_csr_src[slot1] = src1;
    g_csr_ea[slot0] = ea0;
    g_csr_ea[slot1] = ea1;
}

// ---------------- tf32 tensor-core Q/K/V GEMM ----------------
#define XS_STRIDE 44
#define WS_STRIDE 136

__global__ void __launch_bounds__(256) qkv_tc_kernel(
        const float* __restrict__ x,
        const float* __restrict__ Wq, const float* __restrict__ bq,
        const float* __restrict__ Wk, const float* __restrict__ bk,
        const float* __restrict__ Wv, const float* __restrict__ bv) {
    __shared__ float xs[128 * XS_STRIDE];
    __shared__ float ws[32 * WS_STRIDE];

    const int tid  = threadIdx.x;
    const int wid  = tid >> 5;
    const int lane = tid & 31;
    const int g    = lane >> 2;
    const int tg   = lane & 3;
    const int row0 = blockIdx.x * 128;
    const int wm0  = (wid >> 1) * 32;
    const int wn0  = (wid & 1) * 64;

    const float* Ws[3] = {Wq, Wk, Wv};
    const float* bs[3] = {bq, bk, bv};
    float* outs[3];
    outs[0] = g_q; outs[1] = g_k; outs[2] = g_v;

#pragma unroll 1
    for (int which = 0; which < 3; which++) {
        const float* W = Ws[which];
        const float* bb = bs[which];
        float* out = outs[which];

        float acc[2][8][4];
#pragma unroll
        for (int nt = 0; nt < 8; nt++) {
            int n = wn0 + nt * 8 + tg * 2;
            float b0 = bb[n], b1 = bb[n + 1];
#pragma unroll
            for (int mt = 0; mt < 2; mt++) {
                acc[mt][nt][0] = b0; acc[mt][nt][1] = b1;
                acc[mt][nt][2] = b0; acc[mt][nt][3] = b1;
            }
        }

#pragma unroll 1
        for (int kk = 0; kk < 128; kk += 32) {
            __syncthreads();
            for (int i = tid; i < 128 * 8; i += 256) {
                int r = i >> 3, c4 = i & 7;
                float4 v = make_float4(0.f, 0.f, 0.f, 0.f);
                if (row0 + r < NN)
                    v = ((const float4*)x)[(size_t)(row0 + r) * 32 + (kk >> 2) + c4];
                uint32_t* d = (uint32_t*)(xs + r * XS_STRIDE + c4 * 4);
                d[0] = f32_to_tf32(v.x); d[1] = f32_to_tf32(v.y);
                d[2] = f32_to_tf32(v.z); d[3] = f32_to_tf32(v.w);
            }
            for (int i = tid; i < 32 * 32; i += 256) {
                int r = i >> 5, c4 = i & 31;
                float4 v = ((const float4*)W)[(size_t)(kk + r) * 32 + c4];
                uint32_t* d = (uint32_t*)(ws + r * WS_STRIDE + c4 * 4);
                d[0] = f32_to_tf32(v.x); d[1] = f32_to_tf32(v.y);
                d[2] = f32_to_tf32(v.z); d[3] = f32_to_tf32(v.w);
            }
            __syncthreads();

#pragma unroll
            for (int kk2 = 0; kk2 < 32; kk2 += 8) {
                uint32_t afr[2][4];
#pragma unroll
                for (int mt = 0; mt < 2; mt++) {
                    const uint32_t* xr  = (const uint32_t*)(xs + (wm0 + mt * 16 + g) * XS_STRIDE + kk2);
                    const uint32_t* xr8 = (const uint32_t*)(xs + (wm0 + mt * 16 + g + 8) * XS_STRIDE + kk2);
                    afr[mt][0] = xr[tg];
                    afr[mt][1] = xr8[tg];
                    afr[mt][2] = xr[tg + 4];
                    afr[mt][3] = xr8[tg + 4];
                }
#pragma unroll
                for (int nt = 0; nt < 8; nt++) {
                    uint32_t bfr[2];
                    bfr[0] = ((const uint32_t*)(ws + (kk2 + tg) * WS_STRIDE))[wn0 + nt * 8 + g];
                    bfr[1] = ((const uint32_t*)(ws + (kk2 + tg + 4) * WS_STRIDE))[wn0 + nt * 8 + g];
                    mma_tf32(acc[0][nt], afr[0], bfr);
                    mma_tf32(acc[1][nt], afr[1], bfr);
                }
            }
        }

        __syncthreads();
#pragma unroll
        for (int mt = 0; mt < 2; mt++) {
            int rA = row0 + wm0 + mt * 16 + g;
            int rB = rA + 8;
#pragma unroll
            for (int nt = 0; nt < 8; nt++) {
                int n = wn0 + nt * 8 + tg * 2;
                if (rA < NN)
                    *(float2*)(out + (size_t)rA * 128 + n) = make_float2(acc[mt][nt][0], acc[mt][nt][1]);
                if (rB < NN)
                    *(float2*)(out + (size_t)rB * 128 + n) = make_float2(acc[mt][nt][2], acc[mt][nt][3]);
            }
        }
    }
}

// ---------------- fused gather: idx/ea double-buffered pipeline --------------
// one warp per dst node; lane = 4 dims, head = lane/4. 4 warps/block (tail).
__global__ void __launch_bounds__(128) gather_kernel(const float* __restrict__ We,
                                                     const float* __restrict__ be) {
    int node = blockIdx.x * 4 + (threadIdx.x >> 5);
    if (node >= NN) return;
    int lane = threadIdx.x & 31;
    int h = lane >> 2;

    float we0 = We[0 * HH + h], we1 = We[1 * HH + h];
    float we2 = We[2 * HH + h], we3 = We[3 * HH + h];
    float beh = be[h];

    float4 q4 = ((const float4*)g_q)[(size_t)node * 32 + lane];
    int o  = g_off[node];
    int dg = g_deg[node];
    int nIter = dg >> 2;

    float4 acc = make_float4(0.f, 0.f, 0.f, 0.f);
    float sh = 0.f;

    // current-batch registers
    int s0, s1, s2, s3;
    float4 a0, a1, a2, a3;

    if (nIter > 0) {
        s0 = g_csr_src[o + 0];
        s1 = g_csr_src[o + 1];
        s2 = g_csr_src[o + 2];
        s3 = g_csr_src[o + 3];
        a0 = g_csr_ea[o + 0];
        a1 = g_csr_ea[o + 1];
        a2 = g_csr_ea[o + 2];
        a3 = g_csr_ea[o + 3];
    }

    for (int it = 0; it < nIter; it++) {
        // 1) issue k/v loads for the CURRENT batch (indices are resident)
        float4 k0 = ((const float4*)g_k)[(size_t)s0 * 32 + lane];
        float4 k1 = ((const float4*)g_k)[(size_t)s1 * 32 + lane];
        float4 k2 = ((const float4*)g_k)[(size_t)s2 * 32 + lane];
        float4 k3 = ((const float4*)g_k)[(size_t)s3 * 32 + lane];
        float4 v0 = ((const float4*)g_v)[(size_t)s0 * 32 + lane];
        float4 v1 = ((const float4*)g_v)[(size_t)s1 * 32 + lane];
        float4 v2 = ((const float4*)g_v)[(size_t)s2 * 32 + lane];
        float4 v3 = ((const float4*)g_v)[(size_t)s3 * 32 + lane];

        // 2) prefetch NEXT batch idx/ea while k/v are in flight
        int t0 = s0, t1 = s1, t2 = s2, t3 = s3;
        float4 na0 = a0, na1 = a1, na2 = a2, na3 = a3;
        int nb = o + (it + 1) * 4;
        if (it + 1 < nIter) {
            t0 = g_csr_src[nb + 0];
            t1 = g_csr_src[nb + 1];
            t2 = g_csr_src[nb + 2];
            t3 = g_csr_src[nb + 3];
            na0 = g_csr_ea[nb + 0];
            na1 = g_csr_ea[nb + 1];
            na2 = g_csr_ea[nb + 2];
            na3 = g_csr_ea[nb + 3];
        }

        // 3) compute current batch
        float p0 = q4.x * k0.x + q4.y * k0.y + q4.z * k0.z + q4.w * k0.w;
        float p1 = q4.x * k1.x + q4.y * k1.y + q4.z * k1.z + q4.w * k1.w;
        float p2 = q4.x * k2.x + q4.y * k2.y + q4.z * k2.z + q4.w * k2.w;
        float p3 = q4.x * k3.x + q4.y * k3.y + q4.z * k3.z + q4.w * k3.w;
        p0 += __shfl_xor_sync(0xffffffffu, p0, 1);
        p1 += __shfl_xor_sync(0xffffffffu, p1, 1);
        p2 += __shfl_xor_sync(0xffffffffu, p2, 1);
        p3 += __shfl_xor_sync(0xffffffffu, p3, 1);
        p0 += __shfl_xor_sync(0xffffffffu, p0, 2);
        p1 += __shfl_xor_sync(0xffffffffu, p1, 2);
        p2 += __shfl_xor_sync(0xffffffffu, p2, 2);
        p3 += __shfl_xor_sync(0xffffffffu, p3, 2);

        float b0 = a0.x * we0 + a0.y * we1 + a0.z * we2 + a0.w * we3 + beh;
        float b1 = a1.x * we0 + a1.y * we1 + a1.z * we2 + a1.w * we3 + beh;
        float b2 = a2.x * we0 + a2.y * we1 + a2.z * we2 + a2.w * we3 + beh;
        float b3 = a3.x * we0 + a3.y * we1 + a3.z * we2 + a3.w * we3 + beh;

        float e0 = __expf(p0 * 0.25f + b0);
        float e1 = __expf(p1 * 0.25f + b1);
        float e2 = __expf(p2 * 0.25f + b2);
        float e3 = __expf(p3 * 0.25f + b3);
        sh += (e0 + e1) + (e2 + e3);

        acc.x = fmaf(e0, v0.x, acc.x); acc.y = fmaf(e0, v0.y, acc.y);
        acc.z = fmaf(e0, v0.z, acc.z); acc.w = fmaf(e0, v0.w, acc.w);
        acc.x = fmaf(e1, v1.x, acc.x); acc.y = fmaf(e1, v1.y, acc.y);
        acc.z = fmaf(e1, v1.z, acc.z); acc.w = fmaf(e1, v1.w, acc.w);
        acc.x = fmaf(e2, v2.x, acc.x); acc.y = fmaf(e2, v2.y, acc.y);
        acc.z = fmaf(e2, v2.z, acc.z); acc.w = fmaf(e2, v2.w, acc.w);
        acc.x = fmaf(e3, v3.x, acc.x); acc.y = fmaf(e3, v3.y, acc.y);
        acc.z = fmaf(e3, v3.z, acc.z); acc.w = fmaf(e3, v3.w, acc.w);

        // rotate prefetched batch into current
        s0 = t0; s1 = t1; s2 = t2; s3 = t3;
        a0 = na0; a1 = na1; a2 = na2; a3 = na3;
    }

    // remainder edges
    for (int j = nIter * 4; j < dg; j++) {
        int src = g_csr_src[o + j];
        float4 ar = g_csr_ea[o + j];
        float4 k4 = ((const float4*)g_k)[(size_t)src * 32 + lane];
        float p = q4.x * k4.x + q4.y * k4.y + q4.z * k4.z + q4.w * k4.w;
        p += __shfl_xor_sync(0xffffffffu, p, 1);
        p += __shfl_xor_sync(0xffffffffu, p, 2);
        float bias = ar.x * we0 + ar.y * we1 + ar.z * we2 + ar.w * we3 + beh;
        float ex = __expf(p * 0.25f + bias);
        sh += ex;
        float4 v4 = ((const float4*)g_v)[(size_t)src * 32 + lane];
        acc.x = fmaf(ex, v4.x, acc.x);
        acc.y = fmaf(ex, v4.y, acc.y);
        acc.z = fmaf(ex, v4.z, acc.z);
        acc.w = fmaf(ex, v4.w, acc.w);
    }

    float inv = 1.0f / fmaxf(sh, 1e-6f);
    acc.x *= inv; acc.y *= inv; acc.z *= inv; acc.w *= inv;
    ((float4*)g_agg)[(size_t)node * 32 + lane] = acc;
}

// ---------------- Wo GEMM (tf32 TC) + register-resident GroupNorm ------------
__global__ void __launch_bounds__(256) out_gn_tc_kernel(
        const float* __restrict__ Wo, const float* __restrict__ bo,
        const float* __restrict__ gamma, const float* __restrict__ beta,
        float* __restrict__ out) {
    __shared__ float xs[128 * XS_STRIDE];
    __shared__ float ws[32 * WS_STRIDE];

    const int tid  = threadIdx.x;
    const int wid  = tid >> 5;
    const int lane = tid & 31;
    const int g    = lane >> 2;
    const int tg   = lane & 3;
    const int row0 = blockIdx.x * 128;
    const int wm0  = (wid >> 1) * 32;
    const int wn0  = (wid & 1) * 64;

    float acc[2][8][4];
#pragma unroll
    for (int nt = 0; nt < 8; nt++) {
        int n = wn0 + nt * 8 + tg * 2;
        float b0 = bo[n], b1 = bo[n + 1];
#pragma unroll
        for (int mt = 0; mt < 2; mt++) {
            acc[mt][nt][0] = b0; acc[mt][nt][1] = b1;
            acc[mt][nt][2] = b0; acc[mt][nt][3] = b1;
        }
    }

#pragma unroll 1
    for (int kk = 0; kk < 128; kk += 32) {
        __syncthreads();
        for (int i = tid; i < 128 * 8; i += 256) {
            int r = i >> 3, c4 = i & 7;
            float4 v = make_float4(0.f, 0.f, 0.f, 0.f);
            if (row0 + r < NN)
                v = ((const float4*)g_agg)[(size_t)(row0 + r) * 32 + (kk >> 2) + c4];
            uint32_t* d = (uint32_t*)(xs + r * XS_STRIDE + c4 * 4);
            d[0] = f32_to_tf32(v.x); d[1] = f32_to_tf32(v.y);
            d[2] = f32_to_tf32(v.z); d[3] = f32_to_tf32(v.w);
        }
        for (int i = tid; i < 32 * 32; i += 256) {
            int r = i >> 5, c4 = i & 31;
            float4 v = ((const float4*)Wo)[(size_t)(kk + r) * 32 + c4];
            uint32_t* d = (uint32_t*)(ws + r * WS_STRIDE + c4 * 4);
            d[0] = f32_to_tf32(v.x); d[1] = f32_to_tf32(v.y);
            d[2] = f32_to_tf32(v.z); d[3] = f32_to_tf32(v.w);
        }
        __syncthreads();

#pragma unroll
        for (int kk2 = 0; kk2 < 32; kk2 += 8) {
            uint32_t afr[2][4];
#pragma unroll
            for (int mt = 0; mt < 2; mt++) {
                const uint32_t* xr  = (const uint32_t*)(xs + (wm0 + mt * 16 + g) * XS_STRIDE + kk2);
                const uint32_t* xr8 = (const uint32_t*)(xs + (wm0 + mt * 16 + g + 8) * XS_STRIDE + kk2);
                afr[mt][0] = xr[tg];
                afr[mt][1] = xr8[tg];
                afr[mt][2] = xr[tg + 4];
                afr[mt][3] = xr8[tg + 4];
            }
#pragma unroll
            for (int nt = 0; nt < 8; nt++) {
                uint32_t bfr[2];
                bfr[0] = ((const uint32_t*)(ws + (kk2 + tg) * WS_STRIDE))[wn0 + nt * 8 + g];
                bfr[1] = ((const uint32_t*)(ws + (kk2 + tg + 4) * WS_STRIDE))[wn0 + nt * 8 + g];
                mma_tf32(acc[0][nt], afr[0], bfr);
                mma_tf32(acc[1][nt], afr[1], bfr);
            }
        }
    }

#pragma unroll
    for (int mt = 0; mt < 2; mt++) {
        int rA = row0 + wm0 + mt * 16 + g;
        int rB = rA + 8;
#pragma unroll
        for (int gi = 0; gi < 4; gi++) {
            int nt0 = 2 * gi, nt1 = 2 * gi + 1;
            float sA = acc[mt][nt0][0] + acc[mt][nt0][1] + acc[mt][nt1][0] + acc[mt][nt1][1];
            float s2A = acc[mt][nt0][0] * acc[mt][nt0][0] + acc[mt][nt0][1] * acc[mt][nt0][1]
                      + acc[mt][nt1][0] * acc[mt][nt1][0] + acc[mt][nt1][1] * acc[mt][nt1][1];
            float sB = acc[mt][nt0][2] + acc[mt][nt0][3] + acc[mt][nt1][2] + acc[mt][nt1][3];
            float s2B = acc[mt][nt0][2] * acc[mt][nt0][2] + acc[mt][nt0][3] * acc[mt][nt0][3]
                      + acc[mt][nt1][2] * acc[mt][nt1][2] + acc[mt][nt1][3] * acc[mt][nt1][3];
            sA  += __shfl_xor_sync(0xffffffffu, sA, 1);
            s2A += __shfl_xor_sync(0xffffffffu, s2A, 1);
            sB  += __shfl_xor_sync(0xffffffffu, sB, 1);
            s2B += __shfl_xor_sync(0xffffffffu, s2B, 1);
            sA  += __shfl_xor_sync(0xffffffffu, sA, 2);
            s2A += __shfl_xor_sync(0xffffffffu, s2A, 2);
            sB  += __shfl_xor_sync(0xffffffffu, sB, 2);
            s2B += __shfl_xor_sync(0xffffffffu, s2B, 2);

            float muA = sA * (1.0f / 16.0f);
            float varA = s2A * (1.0f / 16.0f) - muA * muA;
            float invA = rsqrtf(varA + EPS_GN);
            float muB = sB * (1.0f / 16.0f);
            float varB = s2B * (1.0f / 16.0f) - muB * muB;
            float invB = rsqrtf(varB + EPS_GN);

            int n0 = wn0 + nt0 * 8 + tg * 2;
            int n1 = wn0 + nt1 * 8 + tg * 2;
            float ga0 = gamma[n0], ga1 = gamma[n0 + 1];
            float ga2 = gamma[n1], ga3 = gamma[n1 + 1];
            float bt0 = beta[n0], bt1 = beta[n0 + 1];
            float bt2 = beta[n1], bt3 = beta[n1 + 1];

            if (rA < NN) {
                *(float2*)(out + (size_t)rA * 128 + n0) = make_float2(
                    (acc[mt][nt0][0] - muA) * invA * ga0 + bt0,
                    (acc[mt][nt0][1] - muA) * invA * ga1 + bt1);
                *(float2*)(out + (size_t)rA * 128 + n1) = make_float2(
                    (acc[mt][nt1][0] - muA) * invA * ga2 + bt2,
                    (acc[mt][nt1][1] - muA) * invA * ga3 + bt3);
            }
            if (rB < NN) {
                *(float2*)(out + (size_t)rB * 128 + n0) = make_float2(
                    (acc[mt][nt0][2] - muB) * invB * ga0 + bt0,
                    (acc[mt][nt0][3] - muB) * invB * ga1 + bt1);
                *(float2*)(out + (size_t)rB * 128 + n1) = make_float2(
                    (acc[mt][nt1][2] - muB) * invB * ga2 + bt2,
                    (acc[mt][nt1][3] - muB) * invB * ga3 + bt3);
            }
        }
    }
}

// ---------------- launch ----------------
extern "C" void kernel_launch(void* const* d_in, const int* in_sizes, int n_in,
                              void* d_out, int out_size) {
    const float* x         = (const float*)d_in[0];
    const int*   ei        = (const int*)d_in[1];   // int32 (JAX downcasts int64 w/o x64 mode)
    const float* edge_attr = (const float*)d_in[2];
    const float* Wq        = (const float*)d_in[3];
    const float* bq        = (const float*)d_in[4];
    const float* Wk        = (const float*)d_in[5];
    const float* bk        = (const float*)d_in[6];
    const float* Wv        = (const float*)d_in[7];
    const float* bv        = (const float*)d_in[8];
    const float* We        = (const float*)d_in[9];
    const float* be        = (const float*)d_in[10];
    const float* Wo        = (const float*)d_in[11];
    const float* bo        = (const float*)d_in[12];
    const float* gamma     = (const float*)d_in[13];
    const float* beta      = (const float*)d_in[14];
    float* out = (float*)d_out;

    // CSR build
    zero_kernel<<<(NN + 255) / 256, 256>>>();
    hist_kernel<<<(EE + 255) / 256, 256>>>(ei);
    scan_kernel<<<1, 1024>>>();
    scatter_kernel<<<(EE / 2 + 255) / 256, 256>>>(ei, edge_attr);

    // projections
    qkv_tc_kernel<<<(NN + 127) / 128, 256>>>(x, Wq, bq, Wk, bk, Wv, bv);

    // fused attention gather (pipelined idx/ea prefetch, 4 warps/block)
    gather_kernel<<<(NN + 3) / 4, 128>>>(We, be);

    // output projection (tf32 TC) + register GroupNorm
    out_gn_tc_kernel<<<(NN + 127) / 128, 256>>>(Wo, bo, gamma, beta, out);
}

// round 13
// speedup vs baseline: 1.4302x; 1.1334x over previous
#include <cuda_runtime.h>
#include <cuda_bf16.h>
#include <float.h>
#include <math.h>
#include <stdint.h>

#define NN 50000
#define DD 128
#define HH 8
#define HDIM 16
#define EE 800000
#define EDIM 4
#define GROUPS 8
#define EPS_GN 1e-5f

// ---------------- scratch (static device globals; no allocation) ----------------
__device__ __align__(16) float g_q[NN * DD];
__device__ __align__(16) float g_k[NN * DD];
__device__ __align__(16) float g_v[NN * DD];
__device__ __align__(16) float g_agg[NN * DD];
__device__ int g_deg[NN];
__device__ int g_cur[NN];
__device__ int g_off[NN + 1];
__device__ int g_csr_src[EE];
__device__ __align__(16) float4 g_csr_ea[EE];

// ---------------- tf32 helpers ----------------
__device__ __forceinline__ uint32_t f32_to_tf32(float f) {
    uint32_t r;
    asm("cvt.rna.tf32.f32 %0, %1;" : "=r"(r) : "f"(f));
    return r;
}

__device__ __forceinline__ void mma_tf32(float* c, const uint32_t* a, const uint32_t* b) {
    asm volatile(
        "mma.sync.aligned.m16n8k8.row.col.f32.tf32.tf32.f32 "
        "{%0,%1,%2,%3}, {%4,%5,%6,%7}, {%8,%9}, {%0,%1,%2,%3};"
        : "+f"(c[0]), "+f"(c[1]), "+f"(c[2]), "+f"(c[3])
        : "r"(a[0]), "r"(a[1]), "r"(a[2]), "r"(a[3]), "r"(b[0]), "r"(b[1]));
}

// ---------------- CSR build ----------------
__global__ void zero_kernel() {
    int i = blockIdx.x * blockDim.x + threadIdx.x;
    if (i < NN) g_deg[i] = 0;
}

__global__ void hist_kernel(const int* __restrict__ ei) {
    int e = blockIdx.x * blockDim.x + threadIdx.x;
    if (e >= EE) return;
    atomicAdd(&g_deg[ei[EE + e]], 1);
}

// single-block exclusive scan of g_deg -> g_off (and g_cur), warp-shfl two-level
__global__ void scan_kernel() {
    __shared__ int warp_sums[32];
    __shared__ int s_carry;
    const int tid  = threadIdx.x;   // 1024 threads
    const int lane = tid & 31;
    const int wid  = tid >> 5;
    if (tid == 0) s_carry = 0;
    __syncthreads();

    for (int base = 0; base < NN; base += 1024) {
        int idx = base + tid;
        int v = (idx < NN) ? g_deg[idx] : 0;
        int x = v;
#pragma unroll
        for (int s = 1; s < 32; s <<= 1) {
            int t = __shfl_up_sync(0xffffffffu, x, s);
            if (lane >= s) x += t;
        }
        if (lane == 31) warp_sums[wid] = x;
        __syncthreads();
        if (wid == 0) {
            int w = warp_sums[lane];
#pragma unroll
            for (int s = 1; s < 32; s <<= 1) {
                int t = __shfl_up_sync(0xffffffffu, w, s);
                if (lane >= s) w += t;
            }
            warp_sums[lane] = w;
        }
        __syncthreads();
        int incl  = x + (wid > 0 ? warp_sums[wid - 1] : 0);
        int carry = s_carry;
        if (idx < NN) {
            int excl = carry + incl - v;
            g_off[idx] = excl;
            g_cur[idx] = excl;
        }
        __syncthreads();
        if (tid == 1023) s_carry = carry + incl;
        __syncthreads();
    }
    if (tid == 0) g_off[NN] = s_carry;
}

// scatter edges into CSR slots (2 edges/thread, front-batched loads)
__global__ void scatter_kernel(const int* __restrict__ ei,
                               const float* __restrict__ edge_attr) {
    int t = blockIdx.x * blockDim.x + threadIdx.x;
    int e0 = t;
    int e1 = t + EE / 2;
    if (e0 >= EE / 2) return;

    int src0 = ei[e0];
    int src1 = ei[e1];
    int dst0 = ei[EE + e0];
    int dst1 = ei[EE + e1];
    float4 ea0 = ((const float4*)edge_attr)[e0];
    float4 ea1 = ((const float4*)edge_attr)[e1];

    int slot0 = atomicAdd(&g_cur[dst0], 1);
    int slot1 = atomicAdd(&g_cur[dst1], 1);
    g_csr_src[slot0] = src0;
    g_csr_src[slot1] = src1;
    g_csr_ea[slot0] = ea0;
    g_csr_ea[slot1] = ea1;
}

// ---------------- tf32 tensor-core Q/K/V GEMM ----------------
#define XS_STRIDE 44
#define WS_STRIDE 136

__global__ void __launch_bounds__(256) qkv_tc_kernel(
        const float* __restrict__ x,
        const float* __restrict__ Wq, const float* __restrict__ bq,
        const float* __restrict__ Wk, const float* __restrict__ bk,
        const float* __restrict__ Wv, const float* __restrict__ bv) {
    __shared__ float xs[128 * XS_STRIDE];
    __shared__ float ws[32 * WS_STRIDE];

    const int tid  = threadIdx.x;
    const int wid  = tid >> 5;
    const int lane = tid & 31;
    const int g    = lane >> 2;
    const int tg   = lane & 3;
    const int row0 = blockIdx.x * 128;
    const int wm0  = (wid >> 1) * 32;
    const int wn0  = (wid & 1) * 64;

    const float* Ws[3] = {Wq, Wk, Wv};
    const float* bs[3] = {bq, bk, bv};
    float* outs[3];
    outs[0] = g_q; outs[1] = g_k; outs[2] = g_v;

#pragma unroll 1
    for (int which = 0; which < 3; which++) {
        const float* W = Ws[which];
        const float* bb = bs[which];
        float* out = outs[which];

        float acc[2][8][4];
#pragma unroll
        for (int nt = 0; nt < 8; nt++) {
            int n = wn0 + nt * 8 + tg * 2;
            float b0 = bb[n], b1 = bb[n + 1];
#pragma unroll
            for (int mt = 0; mt < 2; mt++) {
                acc[mt][nt][0] = b0; acc[mt][nt][1] = b1;
                acc[mt][nt][2] = b0; acc[mt][nt][3] = b1;
            }
        }

#pragma unroll 1
        for (int kk = 0; kk < 128; kk += 32) {
            __syncthreads();
            for (int i = tid; i < 128 * 8; i += 256) {
                int r = i >> 3, c4 = i & 7;
                float4 v = make_float4(0.f, 0.f, 0.f, 0.f);
                if (row0 + r < NN)
                    v = ((const float4*)x)[(size_t)(row0 + r) * 32 + (kk >> 2) + c4];
                uint32_t* d = (uint32_t*)(xs + r * XS_STRIDE + c4 * 4);
                d[0] = f32_to_tf32(v.x); d[1] = f32_to_tf32(v.y);
                d[2] = f32_to_tf32(v.z); d[3] = f32_to_tf32(v.w);
            }
            for (int i = tid; i < 32 * 32; i += 256) {
                int r = i >> 5, c4 = i & 31;
                float4 v = ((const float4*)W)[(size_t)(kk + r) * 32 + c4];
                uint32_t* d = (uint32_t*)(ws + r * WS_STRIDE + c4 * 4);
                d[0] = f32_to_tf32(v.x); d[1] = f32_to_tf32(v.y);
                d[2] = f32_to_tf32(v.z); d[3] = f32_to_tf32(v.w);
            }
            __syncthreads();

#pragma unroll
            for (int kk2 = 0; kk2 < 32; kk2 += 8) {
                uint32_t afr[2][4];
#pragma unroll
                for (int mt = 0; mt < 2; mt++) {
                    const uint32_t* xr  = (const uint32_t*)(xs + (wm0 + mt * 16 + g) * XS_STRIDE + kk2);
                    const uint32_t* xr8 = (const uint32_t*)(xs + (wm0 + mt * 16 + g + 8) * XS_STRIDE + kk2);
                    afr[mt][0] = xr[tg];
                    afr[mt][1] = xr8[tg];
                    afr[mt][2] = xr[tg + 4];
                    afr[mt][3] = xr8[tg + 4];
                }
#pragma unroll
                for (int nt = 0; nt < 8; nt++) {
                    uint32_t bfr[2];
                    bfr[0] = ((const uint32_t*)(ws + (kk2 + tg) * WS_STRIDE))[wn0 + nt * 8 + g];
                    bfr[1] = ((const uint32_t*)(ws + (kk2 + tg + 4) * WS_STRIDE))[wn0 + nt * 8 + g];
                    mma_tf32(acc[0][nt], afr[0], bfr);
                    mma_tf32(acc[1][nt], afr[1], bfr);
                }
            }
        }

        __syncthreads();
#pragma unroll
        for (int mt = 0; mt < 2; mt++) {
            int rA = row0 + wm0 + mt * 16 + g;
            int rB = rA + 8;
#pragma unroll
            for (int nt = 0; nt < 8; nt++) {
                int n = wn0 + nt * 8 + tg * 2;
                if (rA < NN)
                    *(float2*)(out + (size_t)rA * 128 + n) = make_float2(acc[mt][nt][0], acc[mt][nt][1]);
                if (rB < NN)
                    *(float2*)(out + (size_t)rB * 128 + n) = make_float2(acc[mt][nt][2], acc[mt][nt][3]);
            }
        }
    }
}

// ---------------- fused gather: idx/ea double-buffered pipeline --------------
// one warp per dst node; lane = 4 dims, head = lane/4. 4 warps/block (tail).
__global__ void __launch_bounds__(128) gather_kernel(const float* __restrict__ We,
                                                     const float* __restrict__ be) {
    int node = blockIdx.x * 4 + (threadIdx.x >> 5);
    if (node >= NN) return;
    int lane = threadIdx.x & 31;
    int h = lane >> 2;

    float we0 = We[0 * HH + h], we1 = We[1 * HH + h];
    float we2 = We[2 * HH + h], we3 = We[3 * HH + h];
    float beh = be[h];

    float4 q4 = ((const float4*)g_q)[(size_t)node * 32 + lane];
    int o  = g_off[node];
    int dg = g_deg[node];
    int nIter = dg >> 2;

    float4 acc = make_float4(0.f, 0.f, 0.f, 0.f);
    float sh = 0.f;

    int s0, s1, s2, s3;
    float4 a0, a1, a2, a3;

    if (nIter > 0) {
        s0 = g_csr_src[o + 0];
        s1 = g_csr_src[o + 1];
        s2 = g_csr_src[o + 2];
        s3 = g_csr_src[o + 3];
        a0 = g_csr_ea[o + 0];
        a1 = g_csr_ea[o + 1];
        a2 = g_csr_ea[o + 2];
        a3 = g_csr_ea[o + 3];
    }

    for (int it = 0; it < nIter; it++) {
        float4 k0 = ((const float4*)g_k)[(size_t)s0 * 32 + lane];
        float4 k1 = ((const float4*)g_k)[(size_t)s1 * 32 + lane];
        float4 k2 = ((const float4*)g_k)[(size_t)s2 * 32 + lane];
        float4 k3 = ((const float4*)g_k)[(size_t)s3 * 32 + lane];
        float4 v0 = ((const float4*)g_v)[(size_t)s0 * 32 + lane];
        float4 v1 = ((const float4*)g_v)[(size_t)s1 * 32 + lane];
        float4 v2 = ((const float4*)g_v)[(size_t)s2 * 32 + lane];
        float4 v3 = ((const float4*)g_v)[(size_t)s3 * 32 + lane];

        int t0 = s0, t1 = s1, t2 = s2, t3 = s3;
        float4 na0 = a0, na1 = a1, na2 = a2, na3 = a3;
        int nb = o + (it + 1) * 4;
        if (it + 1 < nIter) {
            t0 = g_csr_src[nb + 0];
            t1 = g_csr_src[nb + 1];
            t2 = g_csr_src[nb + 2];
            t3 = g_csr_src[nb + 3];
            na0 = g_csr_ea[nb + 0];
            na1 = g_csr_ea[nb + 1];
            na2 = g_csr_ea[nb + 2];
            na3 = g_csr_ea[nb + 3];
        }

        float p0 = q4.x * k0.x + q4.y * k0.y + q4.z * k0.z + q4.w * k0.w;
        float p1 = q4.x * k1.x + q4.y * k1.y + q4.z * k1.z + q4.w * k1.w;
        float p2 = q4.x * k2.x + q4.y * k2.y + q4.z * k2.z + q4.w * k2.w;
        float p3 = q4.x * k3.x + q4.y * k3.y + q4.z * k3.z + q4.w * k3.w;
        p0 += __shfl_xor_sync(0xffffffffu, p0, 1);
        p1 += __shfl_xor_sync(0xffffffffu, p1, 1);
        p2 += __shfl_xor_sync(0xffffffffu, p2, 1);
        p3 += __shfl_xor_sync(0xffffffffu, p3, 1);
        p0 += __shfl_xor_sync(0xffffffffu, p0, 2);
        p1 += __shfl_xor_sync(0xffffffffu, p1, 2);
        p2 += __shfl_xor_sync(0xffffffffu, p2, 2);
        p3 += __shfl_xor_sync(0xffffffffu, p3, 2);

        float b0 = a0.x * we0 + a0.y * we1 + a0.z * we2 + a0.w * we3 + beh;
        float b1 = a1.x * we0 + a1.y * we1 + a1.z * we2 + a1.w * we3 + beh;
        float b2 = a2.x * we0 + a2.y * we1 + a2.z * we2 + a2.w * we3 + beh;
        float b3 = a3.x * we0 + a3.y * we1 + a3.z * we2 + a3.w * we3 + beh;

        float e0 = __expf(p0 * 0.25f + b0);
        float e1 = __expf(p1 * 0.25f + b1);
        float e2 = __expf(p2 * 0.25f + b2);
        float e3 = __expf(p3 * 0.25f + b3);
        sh += (e0 + e1) + (e2 + e3);

        acc.x = fmaf(e0, v0.x, acc.x); acc.y = fmaf(e0, v0.y, acc.y);
        acc.z = fmaf(e0, v0.z, acc.z); acc.w = fmaf(e0, v0.w, acc.w);
        acc.x = fmaf(e1, v1.x, acc.x); acc.y = fmaf(e1, v1.y, acc.y);
        acc.z = fmaf(e1, v1.z, acc.z); acc.w = fmaf(e1, v1.w, acc.w);
        acc.x = fmaf(e2, v2.x, acc.x); acc.y = fmaf(e2, v2.y, acc.y);
        acc.z = fmaf(e2, v2.z, acc.z); acc.w = fmaf(e2, v2.w, acc.w);
        acc.x = fmaf(e3, v3.x, acc.x); acc.y = fmaf(e3, v3.y, acc.y);
        acc.z = fmaf(e3, v3.z, acc.z); acc.w = fmaf(e3, v3.w, acc.w);

        s0 = t0; s1 = t1; s2 = t2; s3 = t3;
        a0 = na0; a1 = na1; a2 = na2; a3 = na3;
    }

    for (int j = nIter * 4; j < dg; j++) {
        int src = g_csr_src[o + j];
        float4 ar = g_csr_ea[o + j];
        float4 k4 = ((const float4*)g_k)[(size_t)src * 32 + lane];
        float p = q4.x * k4.x + q4.y * k4.y + q4.z * k4.z + q4.w * k4.w;
        p += __shfl_xor_sync(0xffffffffu, p, 1);
        p += __shfl_xor_sync(0xffffffffu, p, 2);
        float bias = ar.x * we0 + ar.y * we1 + ar.z * we2 + ar.w * we3 + beh;
        float ex = __expf(p * 0.25f + bias);
        sh += ex;
        float4 v4 = ((const float4*)g_v)[(size_t)src * 32 + lane];
        acc.x = fmaf(ex, v4.x, acc.x);
        acc.y = fmaf(ex, v4.y, acc.y);
        acc.z = fmaf(ex, v4.z, acc.z);
        acc.w = fmaf(ex, v4.w, acc.w);
    }

    float inv = 1.0f / fmaxf(sh, 1e-6f);
    acc.x *= inv; acc.y *= inv; acc.z *= inv; acc.w *= inv;
    ((float4*)g_agg)[(size_t)node * 32 + lane] = acc;
}

// ---------------- Wo GEMM (tf32 TC) + register-resident GroupNorm ------------
__global__ void __launch_bounds__(256) out_gn_tc_kernel(
        const float* __restrict__ Wo, const float* __restrict__ bo,
        const float* __restrict__ gamma, const float* __restrict__ beta,
        float* __restrict__ out) {
    __shared__ float xs[128 * XS_STRIDE];
    __shared__ float ws[32 * WS_STRIDE];

    const int tid  = threadIdx.x;
    const int wid  = tid >> 5;
    const int lane = tid & 31;
    const int g    = lane >> 2;
    const int tg   = lane & 3;
    const int row0 = blockIdx.x * 128;
    const int wm0  = (wid >> 1) * 32;
    const int wn0  = (wid & 1) * 64;

    float acc[2][8][4];
#pragma unroll
    for (int nt = 0; nt < 8; nt++) {
        int n = wn0 + nt * 8 + tg * 2;
        float b0 = bo[n], b1 = bo[n + 1];
#pragma unroll
        for (int mt = 0; mt < 2; mt++) {
            acc[mt][nt][0] = b0; acc[mt][nt][1] = b1;
            acc[mt][nt][2] = b0; acc[mt][nt][3] = b1;
        }
    }

#pragma unroll 1
    for (int kk = 0; kk < 128; kk += 32) {
        __syncthreads();
        for (int i = tid; i < 128 * 8; i += 256) {
            int r = i >> 3, c4 = i & 7;
            float4 v = make_float4(0.f, 0.f, 0.f, 0.f);
            if (row0 + r < NN)
                v = ((const float4*)g_agg)[(size_t)(row0 + r) * 32 + (kk >> 2) + c4];
            uint32_t* d = (uint32_t*)(xs + r * XS_STRIDE + c4 * 4);
            d[0] = f32_to_tf32(v.x); d[1] = f32_to_tf32(v.y);
            d[2] = f32_to_tf32(v.z); d[3] = f32_to_tf32(v.w);
        }
        for (int i = tid; i < 32 * 32; i += 256) {
            int r = i >> 5, c4 = i & 31;
            float4 v = ((const float4*)Wo)[(size_t)(kk + r) * 32 + c4];
            uint32_t* d = (uint32_t*)(ws + r * WS_STRIDE + c4 * 4);
            d[0] = f32_to_tf32(v.x); d[1] = f32_to_tf32(v.y);
            d[2] = f32_to_tf32(v.z); d[3] = f32_to_tf32(v.w);
        }
        __syncthreads();

#pragma unroll
        for (int kk2 = 0; kk2 < 32; kk2 += 8) {
            uint32_t afr[2][4];
#pragma unroll
            for (int mt = 0; mt < 2; mt++) {
                const uint32_t* xr  = (const uint32_t*)(xs + (wm0 + mt * 16 + g) * XS_STRIDE + kk2);
                const uint32_t* xr8 = (const uint32_t*)(xs + (wm0 + mt * 16 + g + 8) * XS_STRIDE + kk2);
                afr[mt][0] = xr[tg];
                afr[mt][1] = xr8[tg];
                afr[mt][2] = xr[tg + 4];
                afr[mt][3] = xr8[tg + 4];
            }
#pragma unroll
            for (int nt = 0; nt < 8; nt++) {
                uint32_t bfr[2];
                bfr[0] = ((const uint32_t*)(ws + (kk2 + tg) * WS_STRIDE))[wn0 + nt * 8 + g];
                bfr[1] = ((const uint32_t*)(ws + (kk2 + tg + 4) * WS_STRIDE))[wn0 + nt * 8 + g];
                mma_tf32(acc[0][nt], afr[0], bfr);
                mma_tf32(acc[1][nt], afr[1], bfr);
            }
        }
    }

#pragma unroll
    for (int mt = 0; mt < 2; mt++) {
        int rA = row0 + wm0 + mt * 16 + g;
        int rB = rA + 8;
#pragma unroll
        for (int gi = 0; gi < 4; gi++) {
            int nt0 = 2 * gi, nt1 = 2 * gi + 1;
            float sA = acc[mt][nt0][0] + acc[mt][nt0][1] + acc[mt][nt1][0] + acc[mt][nt1][1];
            float s2A = acc[mt][nt0][0] * acc[mt][nt0][0] + acc[mt][nt0][1] * acc[mt][nt0][1]
                      + acc[mt][nt1][0] * acc[mt][nt1][0] + acc[mt][nt1][1] * acc[mt][nt1][1];
            float sB = acc[mt][nt0][2] + acc[mt][nt0][3] + acc[mt][nt1][2] + acc[mt][nt1][3];
            float s2B = acc[mt][nt0][2] * acc[mt][nt0][2] + acc[mt][nt0][3] * acc[mt][nt0][3]
                      + acc[mt][nt1][2] * acc[mt][nt1][2] + acc[mt][nt1][3] * acc[mt][nt1][3];
            sA  += __shfl_xor_sync(0xffffffffu, sA, 1);
            s2A += __shfl_xor_sync(0xffffffffu, s2A, 1);
            sB  += __shfl_xor_sync(0xffffffffu, sB, 1);
            s2B += __shfl_xor_sync(0xffffffffu, s2B, 1);
            sA  += __shfl_xor_sync(0xffffffffu, sA, 2);
            s2A += __shfl_xor_sync(0xffffffffu, s2A, 2);
            sB  += __shfl_xor_sync(0xffffffffu, sB, 2);
            s2B += __shfl_xor_sync(0xffffffffu, s2B, 2);

            float muA = sA * (1.0f / 16.0f);
            float varA = s2A * (1.0f / 16.0f) - muA * muA;
            float invA = rsqrtf(varA + EPS_GN);
            float muB = sB * (1.0f / 16.0f);
            float varB = s2B * (1.0f / 16.0f) - muB * muB;
            float invB = rsqrtf(varB + EPS_GN);

            int n0 = wn0 + nt0 * 8 + tg * 2;
            int n1 = wn0 + nt1 * 8 + tg * 2;
            float ga0 = gamma[n0], ga1 = gamma[n0 + 1];
            float ga2 = gamma[n1], ga3 = gamma[n1 + 1];
            float bt0 = beta[n0], bt1 = beta[n0 + 1];
            float bt2 = beta[n1], bt3 = beta[n1 + 1];

            if (rA < NN) {
                *(float2*)(out + (size_t)rA * 128 + n0) = make_float2(
                    (acc[mt][nt0][0] - muA) * invA * ga0 + bt0,
                    (acc[mt][nt0][1] - muA) * invA * ga1 + bt1);
                *(float2*)(out + (size_t)rA * 128 + n1) = make_float2(
                    (acc[mt][nt1][0] - muA) * invA * ga2 + bt2,
                    (acc[mt][nt1][1] - muA) * invA * ga3 + bt3);
            }
            if (rB < NN) {
                *(float2*)(out + (size_t)rB * 128 + n0) = make_float2(
                    (acc[mt][nt0][2] - muB) * invB * ga0 + bt0,
                    (acc[mt][nt0][3] - muB) * invB * ga1 + bt1);
                *(float2*)(out + (size_t)rB * 128 + n1) = make_float2(
                    (acc[mt][nt1][2] - muB) * invB * ga2 + bt2,
                    (acc[mt][nt1][3] - muB) * invB * ga3 + bt3);
            }
        }
    }
}

// ---------------- launch (fork/join: CSR build || QKV GEMM) ----------------
extern "C" void kernel_launch(void* const* d_in, const int* in_sizes, int n_in,
                              void* d_out, int out_size) {
    const float* x         = (const float*)d_in[0];
    const int*   ei        = (const int*)d_in[1];   // int32 (JAX downcasts int64 w/o x64 mode)
    const float* edge_attr = (const float*)d_in[2];
    const float* Wq        = (const float*)d_in[3];
    const float* bq        = (const float*)d_in[4];
    const float* Wk        = (const float*)d_in[5];
    const float* bk        = (const float*)d_in[6];
    const float* Wv        = (const float*)d_in[7];
    const float* bv        = (const float*)d_in[8];
    const float* We        = (const float*)d_in[9];
    const float* be        = (const float*)d_in[10];
    const float* Wo        = (const float*)d_in[11];
    const float* bo        = (const float*)d_in[12];
    const float* gamma     = (const float*)d_in[13];
    const float* beta      = (const float*)d_in[14];
    float* out = (float*)d_out;

    // lazy one-time stream/event creation (host resources only; no device memory)
    static cudaStream_t s2 = nullptr;
    static cudaEvent_t ev_fork = nullptr, ev_join = nullptr;
    if (s2 == nullptr) {
        cudaStreamCreateWithFlags(&s2, cudaStreamNonBlocking);
        cudaEventCreateWithFlags(&ev_fork, cudaEventDisableTiming);
        cudaEventCreateWithFlags(&ev_join, cudaEventDisableTiming);
    }

    // fork: qkv GEMM on s2, CSR build on the capture (default) stream
    cudaEventRecord(ev_fork, 0);
    cudaStreamWaitEvent(s2, ev_fork, 0);
    qkv_tc_kernel<<<(NN + 127) / 128, 256, 0, s2>>>(x, Wq, bq, Wk, bk, Wv, bv);
    cudaEventRecord(ev_join, s2);

    zero_kernel<<<(NN + 255) / 256, 256>>>();
    hist_kernel<<<(EE + 255) / 256, 256>>>(ei);
    scan_kernel<<<1, 1024>>>();
    scatter_kernel<<<(EE / 2 + 255) / 256, 256>>>(ei, edge_attr);

    // join: gather needs both CSR and q/k/v
    cudaStreamWaitEvent(0, ev_join, 0);

    gather_kernel<<<(NN + 3) / 4, 128>>>(We, be);

    out_gn_tc_kernel<<<(NN + 127) / 128, 256>>>(Wo, bo, gamma, beta, out);
}

// round 15
// speedup vs baseline: 1.4385x; 1.0058x over previous
#include <cuda_runtime.h>
#include <cuda_bf16.h>
#include <float.h>
#include <math.h>
#include <stdint.h>

#define NN 50000
#define DD 128
#define HH 8
#define HDIM 16
#define EE 800000
#define EDIM 4
#define GROUPS 8
#define EPS_GN 1e-5f
#define SCAN_BLOCKS ((NN + 1023) / 1024)   // 49

// ---------------- scratch (static device globals; no allocation) ----------------
__device__ __align__(16) float g_q[NN * DD];
__device__ __align__(16) float g_k[NN * DD];
__device__ __align__(16) float g_v[NN * DD];
__device__ __align__(16) float g_agg[NN * DD];
__device__ int g_deg[NN];
__device__ int g_cur[NN];
__device__ int g_off[NN + 1];
__device__ int g_csr_src[EE];
__device__ __align__(16) float4 g_csr_ea[EE];
__device__ int g_blocksum[64];
__device__ int g_blockoff[64];

// ---------------- tf32 helpers ----------------
__device__ __forceinline__ uint32_t f32_to_tf32(float f) {
    uint32_t r;
    asm("cvt.rna.tf32.f32 %0, %1;" : "=r"(r) : "f"(f));
    return r;
}

__device__ __forceinline__ void mma_tf32(float* c, const uint32_t* a, const uint32_t* b) {
    asm volatile(
        "mma.sync.aligned.m16n8k8.row.col.f32.tf32.tf32.f32 "
        "{%0,%1,%2,%3}, {%4,%5,%6,%7}, {%8,%9}, {%0,%1,%2,%3};"
        : "+f"(c[0]), "+f"(c[1]), "+f"(c[2]), "+f"(c[3])
        : "r"(a[0]), "r"(a[1]), "r"(a[2]), "r"(a[3]), "r"(b[0]), "r"(b[1]));
}

// ---------------- CSR build ----------------
__global__ void zero_kernel() {
    int i = blockIdx.x * blockDim.x + threadIdx.x;
    if (i < NN) g_deg[i] = 0;
}

__global__ void hist_kernel(const int* __restrict__ ei) {
    int e = blockIdx.x * blockDim.x + threadIdx.x;
    if (e >= EE) return;
    atomicAdd(&g_deg[ei[EE + e]], 1);
}

// phase 1: block-local exclusive scan of g_deg -> g_off (no global offset yet),
// block totals -> g_blocksum.
__global__ void scan_part() {
    __shared__ int warp_sums[32];
    const int tid  = threadIdx.x;   // 1024
    const int lane = tid & 31;
    const int wid  = tid >> 5;
    int idx = blockIdx.x * 1024 + tid;

    int v = (idx < NN) ? g_deg[idx] : 0;
    int x = v;
#pragma unroll
    for (int s = 1; s < 32; s <<= 1) {
        int t = __shfl_up_sync(0xffffffffu, x, s);
        if (lane >= s) x += t;
    }
    if (lane == 31) warp_sums[wid] = x;
    __syncthreads();
    if (wid == 0) {
        int w = warp_sums[lane];
#pragma unroll
        for (int s = 1; s < 32; s <<= 1) {
            int t = __shfl_up_sync(0xffffffffu, w, s);
            if (lane >= s) w += t;
        }
        warp_sums[lane] = w;
    }
    __syncthreads();
    int incl = x + (wid > 0 ? warp_sums[wid - 1] : 0);
    if (idx < NN) g_off[idx] = incl - v;          // block-local exclusive
    if (tid == 1023) g_blocksum[blockIdx.x] = incl;  // block total
}

// phase 2: scan the SCAN_BLOCKS block sums (single 64-thread block)
__global__ void scan_bs() {
    __shared__ int warp_sums[2];
    const int tid  = threadIdx.x;   // 64
    const int lane = tid & 31;
    const int wid  = tid >> 5;

    int v = (tid < SCAN_BLOCKS) ? g_blocksum[tid] : 0;
    int x = v;
#pragma unroll
    for (int s = 1; s < 32; s <<= 1) {
        int t = __shfl_up_sync(0xffffffffu, x, s);
        if (lane >= s) x += t;
    }
    if (lane == 31) warp_sums[wid] = x;
    __syncthreads();
    int incl = x + (wid > 0 ? warp_sums[0] : 0);
    if (tid < SCAN_BLOCKS) g_blockoff[tid] = incl - v;
    if (tid == SCAN_BLOCKS - 1) g_off[NN] = incl;
}

// phase 3: add block offsets; mirror into g_cur
__global__ void scan_add() {
    int idx = blockIdx.x * 1024 + threadIdx.x;
    if (idx < NN) {
        int o = g_off[idx] + g_blockoff[blockIdx.x];
        g_off[idx] = o;
        g_cur[idx] = o;
    }
}

// scatter edges into CSR slots (2 edges/thread, front-batched loads)
__global__ void scatter_kernel(const int* __restrict__ ei,
                               const float* __restrict__ edge_attr) {
    int t = blockIdx.x * blockDim.x + threadIdx.x;
    int e0 = t;
    int e1 = t + EE / 2;
    if (e0 >= EE / 2) return;

    int src0 = ei[e0];
    int src1 = ei[e1];
    int dst0 = ei[EE + e0];
    int dst1 = ei[EE + e1];
    float4 ea0 = ((const float4*)edge_attr)[e0];
    float4 ea1 = ((const float4*)edge_attr)[e1];

    int slot0 = atomicAdd(&g_cur[dst0], 1);
    int slot1 = atomicAdd(&g_cur[dst1], 1);
    g_csr_src[slot0] = src0;
    g_csr_src[slot1] = src1;
    g_csr_ea[slot0] = ea0;
    g_csr_ea[slot1] = ea1;
}

// ---------------- tf32 tensor-core Q/K/V GEMM ----------------
#define XS_STRIDE 44
#define WS_STRIDE 136

__global__ void __launch_bounds__(256) qkv_tc_kernel(
        const float* __restrict__ x,
        const float* __restrict__ Wq, const float* __restrict__ bq,
        const float* __restrict__ Wk, const float* __restrict__ bk,
        const float* __restrict__ Wv, const float* __restrict__ bv) {
    __shared__ float xs[128 * XS_STRIDE];
    __shared__ float ws[32 * WS_STRIDE];

    const int tid  = threadIdx.x;
    const int wid  = tid >> 5;
    const int lane = tid & 31;
    const int g    = lane >> 2;
    const int tg   = lane & 3;
    const int row0 = blockIdx.x * 128;
    const int wm0  = (wid >> 1) * 32;
    const int wn0  = (wid & 1) * 64;

    const float* Ws[3] = {Wq, Wk, Wv};
    const float* bs[3] = {bq, bk, bv};
    float* outs[3];
    outs[0] = g_q; outs[1] = g_k; outs[2] = g_v;

#pragma unroll 1
    for (int which = 0; which < 3; which++) {
        const float* W = Ws[which];
        const float* bb = bs[which];
        float* out = outs[which];

        float acc[2][8][4];
#pragma unroll
        for (int nt = 0; nt < 8; nt++) {
            int n = wn0 + nt * 8 + tg * 2;
            float b0 = bb[n], b1 = bb[n + 1];
#pragma unroll
            for (int mt = 0; mt < 2; mt++) {
                acc[mt][nt][0] = b0; acc[mt][nt][1] = b1;
                acc[mt][nt][2] = b0; acc[mt][nt][3] = b1;
            }
        }

#pragma unroll 1
        for (int kk = 0; kk < 128; kk += 32) {
            __syncthreads();
            for (int i = tid; i < 128 * 8; i += 256) {
                int r = i >> 3, c4 = i & 7;
                float4 v = make_float4(0.f, 0.f, 0.f, 0.f);
                if (row0 + r < NN)
                    v = ((const float4*)x)[(size_t)(row0 + r) * 32 + (kk >> 2) + c4];
                uint32_t* d = (uint32_t*)(xs + r * XS_STRIDE + c4 * 4);
                d[0] = f32_to_tf32(v.x); d[1] = f32_to_tf32(v.y);
                d[2] = f32_to_tf32(v.z); d[3] = f32_to_tf32(v.w);
            }
            for (int i = tid; i < 32 * 32; i += 256) {
                int r = i >> 5, c4 = i & 31;
                float4 v = ((const float4*)W)[(size_t)(kk + r) * 32 + c4];
                uint32_t* d = (uint32_t*)(ws + r * WS_STRIDE + c4 * 4);
                d[0] = f32_to_tf32(v.x); d[1] = f32_to_tf32(v.y);
                d[2] = f32_to_tf32(v.z); d[3] = f32_to_tf32(v.w);
            }
            __syncthreads();

#pragma unroll
            for (int kk2 = 0; kk2 < 32; kk2 += 8) {
                uint32_t afr[2][4];
#pragma unroll
                for (int mt = 0; mt < 2; mt++) {
                    const uint32_t* xr  = (const uint32_t*)(xs + (wm0 + mt * 16 + g) * XS_STRIDE + kk2);
                    const uint32_t* xr8 = (const uint32_t*)(xs + (wm0 + mt * 16 + g + 8) * XS_STRIDE + kk2);
                    afr[mt][0] = xr[tg];
                    afr[mt][1] = xr8[tg];
                    afr[mt][2] = xr[tg + 4];
                    afr[mt][3] = xr8[tg + 4];
                }
#pragma unroll
                for (int nt = 0; nt < 8; nt++) {
                    uint32_t bfr[2];
                    bfr[0] = ((const uint32_t*)(ws + (kk2 + tg) * WS_STRIDE))[wn0 + nt * 8 + g];
                    bfr[1] = ((const uint32_t*)(ws + (kk2 + tg + 4) * WS_STRIDE))[wn0 + nt * 8 + g];
                    mma_tf32(acc[0][nt], afr[0], bfr);
                    mma_tf32(acc[1][nt], afr[1], bfr);
                }
            }
        }

        __syncthreads();
#pragma unroll
        for (int mt = 0; mt < 2; mt++) {
            int rA = row0 + wm0 + mt * 16 + g;
            int rB = rA + 8;
#pragma unroll
            for (int nt = 0; nt < 8; nt++) {
                int n = wn0 + nt * 8 + tg * 2;
                if (rA < NN)
                    *(float2*)(out + (size_t)rA * 128 + n) = make_float2(acc[mt][nt][0], acc[mt][nt][1]);
                if (rB < NN)
                    *(float2*)(out + (size_t)rB * 128 + n) = make_float2(acc[mt][nt][2], acc[mt][nt][3]);
            }
        }
    }
}

// ---------------- fused gather: idx/ea double-buffered pipeline --------------
__global__ void __launch_bounds__(128) gather_kernel(const float* __restrict__ We,
                                                     const float* __restrict__ be) {
    int node = blockIdx.x * 4 + (threadIdx.x >> 5);
    if (node >= NN) return;
    int lane = threadIdx.x & 31;
    int h = lane >> 2;

    float we0 = We[0 * HH + h], we1 = We[1 * HH + h];
    float we2 = We[2 * HH + h], we3 = We[3 * HH + h];
    float beh = be[h];

    float4 q4 = ((const float4*)g_q)[(size_t)node * 32 + lane];
    int o  = g_off[node];
    int dg = g_deg[node];
    int nIter = dg >> 2;

    float4 acc = make_float4(0.f, 0.f, 0.f, 0.f);
    float sh = 0.f;

    int s0, s1, s2, s3;
    float4 a0, a1, a2, a3;

    if (nIter > 0) {
        s0 = g_csr_src[o + 0];
        s1 = g_csr_src[o + 1];
        s2 = g_csr_src[o + 2];
        s3 = g_csr_src[o + 3];
        a0 = g_csr_ea[o + 0];
        a1 = g_csr_ea[o + 1];
        a2 = g_csr_ea[o + 2];
        a3 = g_csr_ea[o + 3];
    }

    for (int it = 0; it < nIter; it++) {
        float4 k0 = ((const float4*)g_k)[(size_t)s0 * 32 + lane];
        float4 k1 = ((const float4*)g_k)[(size_t)s1 * 32 + lane];
        float4 k2 = ((const float4*)g_k)[(size_t)s2 * 32 + lane];
        float4 k3 = ((const float4*)g_k)[(size_t)s3 * 32 + lane];
        float4 v0 = ((const float4*)g_v)[(size_t)s0 * 32 + lane];
        float4 v1 = ((const float4*)g_v)[(size_t)s1 * 32 + lane];
        float4 v2 = ((const float4*)g_v)[(size_t)s2 * 32 + lane];
        float4 v3 = ((const float4*)g_v)[(size_t)s3 * 32 + lane];

        int t0 = s0, t1 = s1, t2 = s2, t3 = s3;
        float4 na0 = a0, na1 = a1, na2 = a2, na3 = a3;
        int nb = o + (it + 1) * 4;
        if (it + 1 < nIter) {
            t0 = g_csr_src[nb + 0];
            t1 = g_csr_src[nb + 1];
            t2 = g_csr_src[nb + 2];
            t3 = g_csr_src[nb + 3];
            na0 = g_csr_ea[nb + 0];
            na1 = g_csr_ea[nb + 1];
            na2 = g_csr_ea[nb + 2];
            na3 = g_csr_ea[nb + 3];
        }

        float p0 = q4.x * k0.x + q4.y * k0.y + q4.z * k0.z + q4.w * k0.w;
        float p1 = q4.x * k1.x + q4.y * k1.y + q4.z * k1.z + q4.w * k1.w;
        float p2 = q4.x * k2.x + q4.y * k2.y + q4.z * k2.z + q4.w * k2.w;
        float p3 = q4.x * k3.x + q4.y * k3.y + q4.z * k3.z + q4.w * k3.w;
        p0 += __shfl_xor_sync(0xffffffffu, p0, 1);
        p1 += __shfl_xor_sync(0xffffffffu, p1, 1);
        p2 += __shfl_xor_sync(0xffffffffu, p2, 1);
        p3 += __shfl_xor_sync(0xffffffffu, p3, 1);
        p0 += __shfl_xor_sync(0xffffffffu, p0, 2);
        p1 += __shfl_xor_sync(0xffffffffu, p1, 2);
        p2 += __shfl_xor_sync(0xffffffffu, p2, 2);
        p3 += __shfl_xor_sync(0xffffffffu, p3, 2);

        float b0 = a0.x * we0 + a0.y * we1 + a0.z * we2 + a0.w * we3 + beh;
        float b1 = a1.x * we0 + a1.y * we1 + a1.z * we2 + a1.w * we3 + beh;
        float b2 = a2.x * we0 + a2.y * we1 + a2.z * we2 + a2.w * we3 + beh;
        float b3 = a3.x * we0 + a3.y * we1 + a3.z * we2 + a3.w * we3 + beh;

        float e0 = __expf(p0 * 0.25f + b0);
        float e1 = __expf(p1 * 0.25f + b1);
        float e2 = __expf(p2 * 0.25f + b2);
        float e3 = __expf(p3 * 0.25f + b3);
        sh += (e0 + e1) + (e2 + e3);

        acc.x = fmaf(e0, v0.x, acc.x); acc.y = fmaf(e0, v0.y, acc.y);
        acc.z = fmaf(e0, v0.z, acc.z); acc.w = fmaf(e0, v0.w, acc.w);
        acc.x = fmaf(e1, v1.x, acc.x); acc.y = fmaf(e1, v1.y, acc.y);
        acc.z = fmaf(e1, v1.z, acc.z); acc.w = fmaf(e1, v1.w, acc.w);
        acc.x = fmaf(e2, v2.x, acc.x); acc.y = fmaf(e2, v2.y, acc.y);
        acc.z = fmaf(e2, v2.z, acc.z); acc.w = fmaf(e2, v2.w, acc.w);
        acc.x = fmaf(e3, v3.x, acc.x); acc.y = fmaf(e3, v3.y, acc.y);
        acc.z = fmaf(e3, v3.z, acc.z); acc.w = fmaf(e3, v3.w, acc.w);

        s0 = t0; s1 = t1; s2 = t2; s3 = t3;
        a0 = na0; a1 = na1; a2 = na2; a3 = na3;
    }

    for (int j = nIter * 4; j < dg; j++) {
        int src = g_csr_src[o + j];
        float4 ar = g_csr_ea[o + j];
        float4 k4 = ((const float4*)g_k)[(size_t)src * 32 + lane];
        float p = q4.x * k4.x + q4.y * k4.y + q4.z * k4.z + q4.w * k4.w;
        p += __shfl_xor_sync(0xffffffffu, p, 1);
        p += __shfl_xor_sync(0xffffffffu, p, 2);
        float bias = ar.x * we0 + ar.y * we1 + ar.z * we2 + ar.w * we3 + beh;
        float ex = __expf(p * 0.25f + bias);
        sh += ex;
        float4 v4 = ((const float4*)g_v)[(size_t)src * 32 + lane];
        acc.x = fmaf(ex, v4.x, acc.x);
        acc.y = fmaf(ex, v4.y, acc.y);
        acc.z = fmaf(ex, v4.z, acc.z);
        acc.w = fmaf(ex, v4.w, acc.w);
    }

    float inv = 1.0f / fmaxf(sh, 1e-6f);
    acc.x *= inv; acc.y *= inv; acc.z *= inv; acc.w *= inv;
    ((float4*)g_agg)[(size_t)node * 32 + lane] = acc;
}

// ---------------- Wo GEMM (tf32 TC) + register-resident GroupNorm ------------
__global__ void __launch_bounds__(256) out_gn_tc_kernel(
        const float* __restrict__ Wo, const float* __restrict__ bo,
        const float* __restrict__ gamma, const float* __restrict__ beta,
        float* __restrict__ out) {
    __shared__ float xs[128 * XS_STRIDE];
    __shared__ float ws[32 * WS_STRIDE];

    const int tid  = threadIdx.x;
    const int wid  = tid >> 5;
    const int lane = tid & 31;
    const int g    = lane >> 2;
    const int tg   = lane & 3;
    const int row0 = blockIdx.x * 128;
    const int wm0  = (wid >> 1) * 32;
    const int wn0  = (wid & 1) * 64;

    float acc[2][8][4];
#pragma unroll
    for (int nt = 0; nt < 8; nt++) {
        int n = wn0 + nt * 8 + tg * 2;
        float b0 = bo[n], b1 = bo[n + 1];
#pragma unroll
        for (int mt = 0; mt < 2; mt++) {
            acc[mt][nt][0] = b0; acc[mt][nt][1] = b1;
            acc[mt][nt][2] = b0; acc[mt][nt][3] = b1;
        }
    }

#pragma unroll 1
    for (int kk = 0; kk < 128; kk += 32) {
        __syncthreads();
        for (int i = tid; i < 128 * 8; i += 256) {
            int r = i >> 3, c4 = i & 7;
            float4 v = make_float4(0.f, 0.f, 0.f, 0.f);
            if (row0 + r < NN)
                v = ((const float4*)g_agg)[(size_t)(row0 + r) * 32 + (kk >> 2) + c4];
            uint32_t* d = (uint32_t*)(xs + r * XS_STRIDE + c4 * 4);
            d[0] = f32_to_tf32(v.x); d[1] = f32_to_tf32(v.y);
            d[2] = f32_to_tf32(v.z); d[3] = f32_to_tf32(v.w);
        }
        for (int i = tid; i < 32 * 32; i += 256) {
            int r = i >> 5, c4 = i & 31;
            float4 v = ((const float4*)Wo)[(size_t)(kk + r) * 32 + c4];
            uint32_t* d = (uint32_t*)(ws + r * WS_STRIDE + c4 * 4);
            d[0] = f32_to_tf32(v.x); d[1] = f32_to_tf32(v.y);
            d[2] = f32_to_tf32(v.z); d[3] = f32_to_tf32(v.w);
        }
        __syncthreads();

#pragma unroll
        for (int kk2 = 0; kk2 < 32; kk2 += 8) {
            uint32_t afr[2][4];
#pragma unroll
            for (int mt = 0; mt < 2; mt++) {
                const uint32_t* xr  = (const uint32_t*)(xs + (wm0 + mt * 16 + g) * XS_STRIDE + kk2);
                const uint32_t* xr8 = (const uint32_t*)(xs + (wm0 + mt * 16 + g + 8) * XS_STRIDE + kk2);
                afr[mt][0] = xr[tg];
                afr[mt][1] = xr8[tg];
                afr[mt][2] = xr[tg + 4];
                afr[mt][3] = xr8[tg + 4];
            }
#pragma unroll
            for (int nt = 0; nt < 8; nt++) {
                uint32_t bfr[2];
                bfr[0] = ((const uint32_t*)(ws + (kk2 + tg) * WS_STRIDE))[wn0 + nt * 8 + g];
                bfr[1] = ((const uint32_t*)(ws + (kk2 + tg + 4) * WS_STRIDE))[wn0 + nt * 8 + g];
                mma_tf32(acc[0][nt], afr[0], bfr);
                mma_tf32(acc[1][nt], afr[1], bfr);
            }
        }
    }

#pragma unroll
    for (int mt = 0; mt < 2; mt++) {
        int rA = row0 + wm0 + mt * 16 + g;
        int rB = rA + 8;
#pragma unroll
        for (int gi = 0; gi < 4; gi++) {
            int nt0 = 2 * gi, nt1 = 2 * gi + 1;
            float sA = acc[mt][nt0][0] + acc[mt][nt0][1] + acc[mt][nt1][0] + acc[mt][nt1][1];
            float s2A = acc[mt][nt0][0] * acc[mt][nt0][0] + acc[mt][nt0][1] * acc[mt][nt0][1]
                      + acc[mt][nt1][0] * acc[mt][nt1][0] + acc[mt][nt1][1] * acc[mt][nt1][1];
            float sB = acc[mt][nt0][2] + acc[mt][nt0][3] + acc[mt][nt1][2] + acc[mt][nt1][3];
            float s2B = acc[mt][nt0][2] * acc[mt][nt0][2] + acc[mt][nt0][3] * acc[mt][nt0][3]
                      + acc[mt][nt1][2] * acc[mt][nt1][2] + acc[mt][nt1][3] * acc[mt][nt1][3];
            sA  += __shfl_xor_sync(0xffffffffu, sA, 1);
            s2A += __shfl_xor_sync(0xffffffffu, s2A, 1);
            sB  += __shfl_xor_sync(0xffffffffu, sB, 1);
            s2B += __shfl_xor_sync(0xffffffffu, s2B, 1);
            sA  += __shfl_xor_sync(0xffffffffu, sA, 2);
            s2A += __shfl_xor_sync(0xffffffffu, s2A, 2);
            sB  += __shfl_xor_sync(0xffffffffu, sB, 2);
            s2B += __shfl_xor_sync(0xffffffffu, s2B, 2);

            float muA = sA * (1.0f / 16.0f);
            float varA = s2A * (1.0f / 16.0f) - muA * muA;
            float invA = rsqrtf(varA + EPS_GN);
            float muB = sB * (1.0f / 16.0f);
            float varB = s2B * (1.0f / 16.0f) - muB * muB;
            float invB = rsqrtf(varB + EPS_GN);

            int n0 = wn0 + nt0 * 8 + tg * 2;
            int n1 = wn0 + nt1 * 8 + tg * 2;
            float ga0 = gamma[n0], ga1 = gamma[n0 + 1];
            float ga2 = gamma[n1], ga3 = gamma[n1 + 1];
            float bt0 = beta[n0], bt1 = beta[n0 + 1];
            float bt2 = beta[n1], bt3 = beta[n1 + 1];

            if (rA < NN) {
                *(float2*)(out + (size_t)rA * 128 + n0) = make_float2(
                    (acc[mt][nt0][0] - muA) * invA * ga0 + bt0,
                    (acc[mt][nt0][1] - muA) * invA * ga1 + bt1);
                *(float2*)(out + (size_t)rA * 128 + n1) = make_float2(
                    (acc[mt][nt1][0] - muA) * invA * ga2 + bt2,
                    (acc[mt][nt1][1] - muA) * invA * ga3 + bt3);
            }
            if (rB < NN) {
                *(float2*)(out + (size_t)rB * 128 + n0) = make_float2(
                    (acc[mt][nt0][2] - muB) * invB * ga0 + bt0,
                    (acc[mt][nt0][3] - muB) * invB * ga1 + bt1);
                *(float2*)(out + (size_t)rB * 128 + n1) = make_float2(
                    (acc[mt][nt1][2] - muB) * invB * ga2 + bt2,
                    (acc[mt][nt1][3] - muB) * invB * ga3 + bt3);
            }
        }
    }
}

// ---------------- launch (fork/join: CSR build || QKV GEMM) ----------------
extern "C" void kernel_launch(void* const* d_in, const int* in_sizes, int n_in,
                              void* d_out, int out_size) {
    const float* x         = (const float*)d_in[0];
    const int*   ei        = (const int*)d_in[1];   // int32 (JAX downcasts int64 w/o x64 mode)
    const float* edge_attr = (const float*)d_in[2];
    const float* Wq        = (const float*)d_in[3];
    const float* bq        = (const float*)d_in[4];
    const float* Wk        = (const float*)d_in[5];
    const float* bk        = (const float*)d_in[6];
    const float* Wv        = (const float*)d_in[7];
    const float* bv        = (const float*)d_in[8];
    const float* We        = (const float*)d_in[9];
    const float* be        = (const float*)d_in[10];
    const float* Wo        = (const float*)d_in[11];
    const float* bo        = (const float*)d_in[12];
    const float* gamma     = (const float*)d_in[13];
    const float* beta      = (const float*)d_in[14];
    float* out = (float*)d_out;

    // lazy one-time stream/event creation (host resources only; no device memory)
    static cudaStream_t s2 = nullptr;
    static cudaEvent_t ev_fork = nullptr, ev_join = nullptr;
    if (s2 == nullptr) {
        cudaStreamCreateWithFlags(&s2, cudaStreamNonBlocking);
        cudaEventCreateWithFlags(&ev_fork, cudaEventDisableTiming);
        cudaEventCreateWithFlags(&ev_join, cudaEventDisableTiming);
    }

    // fork: qkv GEMM on s2, CSR build on the capture (default) stream
    cudaEventRecord(ev_fork, 0);
    cudaStreamWaitEvent(s2, ev_fork, 0);
    qkv_tc_kernel<<<(NN + 127) / 128, 256, 0, s2>>>(x, Wq, bq, Wk, bk, Wv, bv);
    cudaEventRecord(ev_join, s2);

    zero_kernel<<<(NN + 255) / 256, 256>>>();
    hist_kernel<<<(EE + 255) / 256, 256>>>(ei);
    scan_part<<<SCAN_BLOCKS, 1024>>>();
    scan_bs<<<1, 64>>>();
    scan_add<<<SCAN_BLOCKS, 1024>>>();
    scatter_kernel<<<(EE / 2 + 255) / 256, 256>>>(ei, edge_attr);

    // join: gather needs both CSR and q/k/v
    cudaStreamWaitEvent(0, ev_join, 0);

    gather_kernel<<<(NN + 3) / 4, 128>>>(We, be);

    out_gn_tc_kernel<<<(NN + 127) / 128, 256>>>(Wo, bo, gamma, beta, out);
}